// round 4
// baseline (speedup 1.0000x reference)
#include <cuda_runtime.h>
#include <cuda_bf16.h>
#include <cstdint>

// Problem constants
#define Hd   128
#define Wd   128
#define CIN  64
#define HWd  (Hd * Wd)

// Conv tiling
#define TW   32   // tile width  (pixels)
#define TH   16   // tile height (pixels) -> 2 rows per thread
#define OCB  16   // output channels per block
#define ICB  16   // input-channel chunk staged in smem

// Scratch (allocations are forbidden; device globals are the sanctioned path)
__device__ float g_off [8 * 128 * Hd * Wd];   // offsets: (B, 2C, H, W)  = 67 MB
__device__ float g_xdef[8 *  64 * Hd * Wd];   // deformed x: (B, C, H, W) = 33.5 MB

// ---------------------------------------------------------------------------
// Direct 3x3 conv, pad=1, stride=1. Input (B,CIN,H,W), weights OIHW.
// Block = 32x8 threads; each thread computes 2 vertically-adjacent pixels
// for OCB output channels. grid = (W/TW, H/TH, B * Cout/OCB).
// ---------------------------------------------------------------------------
__global__ void __launch_bounds__(256)
conv3x3_kernel(const float* __restrict__ in,
               const float* __restrict__ wgt,
               const float* __restrict__ bias,
               float* __restrict__ out,
               int Cout)
{
    const int tx = threadIdx.x;            // 0..31
    const int ty = threadIdx.y;            // 0..7
    const int tid = ty * 32 + tx;          // 0..255

    const int tile_x = blockIdx.x * TW;
    const int tile_y = blockIdx.y * TH;
    const int nocg   = Cout / OCB;
    const int ocg    = blockIdx.z % nocg;
    const int b      = blockIdx.z / nocg;
    const int oc0    = ocg * OCB;

    __shared__ float s_in[ICB][TH + 2][TW + 2];   // 16*18*34*4 = 39168 B
    __shared__ float s_w [ICB][OCB][9];           // 16*16*9*4  =  9216 B

    float acc0[OCB], acc1[OCB];
#pragma unroll
    for (int o = 0; o < OCB; o++) {
        const float bv = bias ? bias[oc0 + o] : 0.0f;
        acc0[o] = bv; acc1[o] = bv;
    }

    const float* in_b = in + (size_t)b * CIN * HWd;

    for (int ic0 = 0; ic0 < CIN; ic0 += ICB) {
        // ---- stage input tile (with halo) ----
        const int IN_ELEMS = ICB * (TH + 2) * (TW + 2);
        for (int idx = tid; idx < IN_ELEMS; idx += 256) {
            const int ic = idx / ((TH + 2) * (TW + 2));
            const int r  = idx % ((TH + 2) * (TW + 2));
            const int yy = r / (TW + 2);
            const int xx = r % (TW + 2);
            const int gy = tile_y + yy - 1;
            const int gx = tile_x + xx - 1;
            float v = 0.0f;
            if ((unsigned)gy < (unsigned)Hd && (unsigned)gx < (unsigned)Wd)
                v = in_b[((ic0 + ic) * Hd + gy) * Wd + gx];
            s_in[ic][yy][xx] = v;
        }
        // ---- stage weights for this (oc-block, ic-chunk): 2304 elems = 9/thread ----
        for (int idx = tid; idx < ICB * OCB * 9; idx += 256) {
            const int ic = idx / (OCB * 9);
            const int r  = idx % (OCB * 9);
            const int o  = r / 9;
            const int k  = r % 9;
            s_w[ic][o][k] = wgt[((size_t)(oc0 + o) * CIN + (ic0 + ic)) * 9 + k];
        }
        __syncthreads();

#pragma unroll 1
        for (int ic = 0; ic < ICB; ic++) {
            // 4 rows x 3 cols covers both 3x3 windows (rows ty*2 .. ty*2+3)
            float pv[4][3];
#pragma unroll
            for (int r = 0; r < 4; r++)
#pragma unroll
                for (int c = 0; c < 3; c++)
                    pv[r][c] = s_in[ic][ty * 2 + r][tx + c];

#pragma unroll
            for (int o = 0; o < OCB; o++) {
#pragma unroll
                for (int ky = 0; ky < 3; ky++) {
#pragma unroll
                    for (int kx = 0; kx < 3; kx++) {
                        const float w = s_w[ic][o][ky * 3 + kx];
                        acc0[o] = fmaf(pv[ky    ][kx], w, acc0[o]);
                        acc1[o] = fmaf(pv[ky + 1][kx], w, acc1[o]);
                    }
                }
            }
        }
        __syncthreads();
    }

    const int gy0 = tile_y + ty * 2;
    const int gx  = tile_x + tx;
    float* out_b = out + (size_t)b * Cout * HWd;
#pragma unroll
    for (int o = 0; o < OCB; o++) {
        out_b[((oc0 + o) * Hd + gy0    ) * Wd + gx] = acc0[o];
        out_b[((oc0 + o) * Hd + gy0 + 1) * Wd + gx] = acc1[o];
    }
}

// ---------------------------------------------------------------------------
// Deformable gather: torch-contiguous (b,2c,h,w) -> (b*c, h*w, 2) reinterleave,
// clamped floor/ceil 4-corner bilinear. One thread per output element.
// grid = (HW/256, C, B), block = 256.
// ---------------------------------------------------------------------------
__global__ void __launch_bounds__(256)
gather_kernel(const float* __restrict__ x,
              const float* __restrict__ off,   // (B, 2C, H, W)
              float* __restrict__ xdef)        // (B, C, H, W)
{
    const int p = blockIdx.x * 256 + threadIdx.x;   // 0..HW-1
    const int c = blockIdx.y;                       // 0..63
    const int b = blockIdx.z;                       // 0..7

    // flat offset index within batch: (2c)*HW + 2p + comp
    const int t   = 2 * p;
    const int ch  = 2 * c + (t >> 14);              // t / HW   (HW = 16384)
    const int pos = t & (HWd - 1);                  // t % HW   (even -> float2 aligned)
    const float2 o2 = *reinterpret_cast<const float2*>(
        off + ((size_t)b * (2 * CIN) + ch) * HWd + pos);

    const float gy = (float)(p >> 7);               // p / 128
    const float gx = (float)(p & 127);              // p % 128

    float cy = o2.x + gy;
    float cx = o2.y + gx;
    cy = fminf(fmaxf(cy, 0.0f), (float)(Hd - 1));
    cx = fminf(fmaxf(cx, 0.0f), (float)(Wd - 1));

    const float y0f = floorf(cy), y1f = ceilf(cy);
    const float x0f = floorf(cx), x1f = ceilf(cx);
    const int y0 = (int)y0f, y1 = (int)y1f;
    const int x0 = (int)x0f, x1 = (int)x1f;

    const float* xp = x + ((size_t)b * CIN + c) * HWd;
    const float v_lt = xp[y0 * Wd + x0];   // (floor y, floor x)
    const float v_rb = xp[y1 * Wd + x1];   // (ceil y,  ceil x)
    const float v_lb = xp[y0 * Wd + x1];   // (floor y, ceil x)
    const float v_rt = xp[y1 * Wd + x0];   // (ceil y,  floor x)

    const float dy = cy - y0f;
    const float dx = cx - x0f;
    const float v_t = dy * (v_rt - v_lt) + v_lt;
    const float v_b = dy * (v_rb - v_lb) + v_lb;

    xdef[((size_t)b * CIN + c) * HWd + p] = dx * (v_b - v_t) + v_t;
}

// ---------------------------------------------------------------------------
// kernel_launch: conv(offsets) -> gather -> conv(+bias)
// inputs: d_in[0]=x (B,C,H,W) f32, d_in[1]=W_off (2C,C,3,3), d_in[2]=W_conv
//         (C,C,3,3), d_in[3]=b_conv (C,)
// ---------------------------------------------------------------------------
extern "C" void kernel_launch(void* const* d_in, const int* in_sizes, int n_in,
                              void* d_out, int out_size)
{
    const float* x      = (const float*)d_in[0];
    const float* W_off  = (const float*)d_in[1];
    const float* W_conv = (const float*)d_in[2];
    const float* b_conv = (const float*)d_in[3];
    float* out = (float*)d_out;

    float *off_ptr = nullptr, *xdef_ptr = nullptr;
    cudaGetSymbolAddress((void**)&off_ptr,  g_off);
    cudaGetSymbolAddress((void**)&xdef_ptr, g_xdef);

    const dim3 blk(32, 8);

    // 1) offset conv: 64 -> 128 channels
    conv3x3_kernel<<<dim3(Wd / TW, Hd / TH, 8 * (128 / OCB)), blk>>>(
        x, W_off, nullptr, off_ptr, 128);

    // 2) deformable bilinear gather
    gather_kernel<<<dim3(HWd / 256, CIN, 8), 256>>>(x, off_ptr, xdef_ptr);

    // 3) main conv: 64 -> 64 channels, + bias
    conv3x3_kernel<<<dim3(Wd / TW, Hd / TH, 8 * (64 / OCB)), blk>>>(
        xdef_ptr, W_conv, b_conv, out, 64);
}

// round 5
// speedup vs baseline: 1.0559x; 1.0559x over previous
#include <cuda_runtime.h>
#include <cuda_bf16.h>
#include <cstdint>

// Problem constants
#define Hd   128
#define Wd   128
#define CIN  64
#define HWd  (Hd * Wd)

// Conv tiling
#define TW   32   // tile width  (pixels)
#define TH   16   // tile height (pixels) -> 2 rows per thread
#define OCB  16   // output channels per block (8 packed pairs)
#define ICB  16   // input-channel chunk staged in smem

// Scratch (allocations are forbidden; device globals are the sanctioned path)
__device__ float g_off [8 * 128 * Hd * Wd];   // offsets: (B, 2C, H, W)
__device__ float g_xdef[8 *  64 * Hd * Wd];   // deformed x: (B, C, H, W)

// ---- packed f32x2 helpers (Blackwell FFMA2 path; ptxas never auto-fuses) ----
__device__ __forceinline__ unsigned long long pack2(float lo, float hi) {
    unsigned long long r;
    asm("mov.b64 %0, {%1, %2};" : "=l"(r) : "f"(lo), "f"(hi));
    return r;
}
__device__ __forceinline__ unsigned long long bcast2(float v) {
    unsigned long long r;
    asm("mov.b64 %0, {%1, %1};" : "=l"(r) : "f"(v));
    return r;
}
__device__ __forceinline__ void fma2(unsigned long long& d,
                                     unsigned long long a,
                                     unsigned long long b) {
    asm("fma.rn.f32x2 %0, %1, %2, %0;" : "+l"(d) : "l"(a), "l"(b));
}
__device__ __forceinline__ void unpack2(unsigned long long v, float& lo, float& hi) {
    asm("mov.b64 {%0, %1}, %2;" : "=f"(lo), "=f"(hi) : "l"(v));
}

// ---------------------------------------------------------------------------
// Direct 3x3 conv, pad=1, stride=1, packed-f32x2 over output-channel pairs.
// Block = 32x8 threads; each thread computes 2 vertically-adjacent pixels
// for OCB output channels. grid = (W/TW, H/TH, B * Cout/OCB).
// ---------------------------------------------------------------------------
__global__ void __launch_bounds__(256)
conv3x3_kernel(const float* __restrict__ in,
               const float* __restrict__ wgt,
               const float* __restrict__ bias,
               float* __restrict__ out,
               int Cout)
{
    const int tx = threadIdx.x;            // 0..31
    const int ty = threadIdx.y;            // 0..7
    const int tid = ty * 32 + tx;          // 0..255

    const int tile_x = blockIdx.x * TW;
    const int tile_y = blockIdx.y * TH;
    const int nocg   = Cout / OCB;
    const int ocg    = blockIdx.z % nocg;
    const int b      = blockIdx.z / nocg;
    const int oc0    = ocg * OCB;

    __shared__ float s_in[ICB][TH + 2][TW + 2];                 // 39168 B
    __shared__ __align__(16) float s_w[ICB][9][OCB];            //  9216 B  (oc contiguous!)

    // packed accumulators: pair = (oc 2o, oc 2o+1); one set per pixel row
    unsigned long long accp0[OCB / 2], accp1[OCB / 2];
#pragma unroll
    for (int o = 0; o < OCB / 2; o++) {
        const float b0 = bias ? bias[oc0 + 2 * o]     : 0.0f;
        const float b1 = bias ? bias[oc0 + 2 * o + 1] : 0.0f;
        accp0[o] = pack2(b0, b1);
        accp1[o] = pack2(b0, b1);
    }

    const float* in_b = in + (size_t)b * CIN * HWd;

    for (int ic0 = 0; ic0 < CIN; ic0 += ICB) {
        // ---- stage input tile (with halo) ----
        const int IN_ELEMS = ICB * (TH + 2) * (TW + 2);
        for (int idx = tid; idx < IN_ELEMS; idx += 256) {
            const int ic = idx / ((TH + 2) * (TW + 2));
            const int r  = idx % ((TH + 2) * (TW + 2));
            const int yy = r / (TW + 2);
            const int xx = r % (TW + 2);
            const int gy = tile_y + yy - 1;
            const int gx = tile_x + xx - 1;
            float v = 0.0f;
            if ((unsigned)gy < (unsigned)Hd && (unsigned)gx < (unsigned)Wd)
                v = in_b[((ic0 + ic) * Hd + gy) * Wd + gx];
            s_in[ic][yy][xx] = v;
        }
        // ---- stage weights: layout [ic][k][oc] so oc-pairs are LDS.64 ----
        for (int idx = tid; idx < ICB * 9 * OCB; idx += 256) {
            const int ic = idx / (9 * OCB);
            const int r  = idx % (9 * OCB);
            const int k  = r / OCB;
            const int o  = r % OCB;
            s_w[ic][k][o] = wgt[((size_t)(oc0 + o) * CIN + (ic0 + ic)) * 9 + k];
        }
        __syncthreads();

#pragma unroll 1
        for (int ic = 0; ic < ICB; ic++) {
            // 4 rows x 3 cols covers both 3x3 windows; broadcast-pack each once
            unsigned long long pb[4][3];
#pragma unroll
            for (int r = 0; r < 4; r++)
#pragma unroll
                for (int c = 0; c < 3; c++)
                    pb[r][c] = bcast2(s_in[ic][ty * 2 + r][tx + c]);

            const unsigned long long* wrow =
                reinterpret_cast<const unsigned long long*>(&s_w[ic][0][0]);
#pragma unroll
            for (int ky = 0; ky < 3; ky++) {
#pragma unroll
                for (int kx = 0; kx < 3; kx++) {
                    const int k = ky * 3 + kx;
#pragma unroll
                    for (int o = 0; o < OCB / 2; o++) {
                        const unsigned long long wp = wrow[k * (OCB / 2) + o];
                        fma2(accp0[o], pb[ky    ][kx], wp);
                        fma2(accp1[o], pb[ky + 1][kx], wp);
                    }
                }
            }
        }
        __syncthreads();
    }

    const int gy0 = tile_y + ty * 2;
    const int gx  = tile_x + tx;
    float* out_b = out + (size_t)b * Cout * HWd;
#pragma unroll
    for (int o = 0; o < OCB / 2; o++) {
        float a0, a1, c0, c1;
        unpack2(accp0[o], a0, a1);
        unpack2(accp1[o], c0, c1);
        out_b[((oc0 + 2 * o    ) * Hd + gy0    ) * Wd + gx] = a0;
        out_b[((oc0 + 2 * o + 1) * Hd + gy0    ) * Wd + gx] = a1;
        out_b[((oc0 + 2 * o    ) * Hd + gy0 + 1) * Wd + gx] = c0;
        out_b[((oc0 + 2 * o + 1) * Hd + gy0 + 1) * Wd + gx] = c1;
    }
}

// ---------------------------------------------------------------------------
// Deformable gather: torch-contiguous (b,2c,h,w) -> (b*c, h*w, 2) reinterleave,
// clamped floor/ceil 4-corner bilinear. One thread per output element.
// ---------------------------------------------------------------------------
__global__ void __launch_bounds__(256)
gather_kernel(const float* __restrict__ x,
              const float* __restrict__ off,   // (B, 2C, H, W)
              float* __restrict__ xdef)        // (B, C, H, W)
{
    const int p = blockIdx.x * 256 + threadIdx.x;   // 0..HW-1
    const int c = blockIdx.y;                       // 0..63
    const int b = blockIdx.z;                       // 0..7

    const int t   = 2 * p;
    const int ch  = 2 * c + (t >> 14);              // t / HW   (HW = 16384)
    const int pos = t & (HWd - 1);                  // t % HW
    const float2 o2 = *reinterpret_cast<const float2*>(
        off + ((size_t)b * (2 * CIN) + ch) * HWd + pos);

    const float gy = (float)(p >> 7);
    const float gx = (float)(p & 127);

    float cy = o2.x + gy;
    float cx = o2.y + gx;
    cy = fminf(fmaxf(cy, 0.0f), (float)(Hd - 1));
    cx = fminf(fmaxf(cx, 0.0f), (float)(Wd - 1));

    const float y0f = floorf(cy), y1f = ceilf(cy);
    const float x0f = floorf(cx), x1f = ceilf(cx);
    const int y0 = (int)y0f, y1 = (int)y1f;
    const int x0 = (int)x0f, x1 = (int)x1f;

    const float* xp = x + ((size_t)b * CIN + c) * HWd;
    const float v_lt = xp[y0 * Wd + x0];
    const float v_rb = xp[y1 * Wd + x1];
    const float v_lb = xp[y0 * Wd + x1];
    const float v_rt = xp[y1 * Wd + x0];

    const float dy = cy - y0f;
    const float dx = cx - x0f;
    const float v_t = dy * (v_rt - v_lt) + v_lt;
    const float v_b = dy * (v_rb - v_lb) + v_lb;

    xdef[((size_t)b * CIN + c) * HWd + p] = dx * (v_b - v_t) + v_t;
}

// ---------------------------------------------------------------------------
// kernel_launch: conv(offsets) -> gather -> conv(+bias)
// ---------------------------------------------------------------------------
extern "C" void kernel_launch(void* const* d_in, const int* in_sizes, int n_in,
                              void* d_out, int out_size)
{
    const float* x      = (const float*)d_in[0];
    const float* W_off  = (const float*)d_in[1];
    const float* W_conv = (const float*)d_in[2];
    const float* b_conv = (const float*)d_in[3];
    float* out = (float*)d_out;

    float *off_ptr = nullptr, *xdef_ptr = nullptr;
    cudaGetSymbolAddress((void**)&off_ptr,  g_off);
    cudaGetSymbolAddress((void**)&xdef_ptr, g_xdef);

    const dim3 blk(32, 8);

    // 1) offset conv: 64 -> 128 channels
    conv3x3_kernel<<<dim3(Wd / TW, Hd / TH, 8 * (128 / OCB)), blk>>>(
        x, W_off, nullptr, off_ptr, 128);

    // 2) deformable bilinear gather
    gather_kernel<<<dim3(HWd / 256, CIN, 8), 256>>>(x, off_ptr, xdef_ptr);

    // 3) main conv: 64 -> 64 channels, + bias
    conv3x3_kernel<<<dim3(Wd / TW, Hd / TH, 8 * (64 / OCB)), blk>>>(
        xdef_ptr, W_conv, b_conv, out, 64);
}

// round 7
// speedup vs baseline: 2.1541x; 2.0400x over previous
#include <cuda_runtime.h>
#include <cuda_fp16.h>
#include <cstdint>

#define Hd   128
#define Wd   128
#define CIN  64
#define HWd  (Hd * Wd)
#define Bn   8

// ---------------- scratch (device globals; allocation is forbidden) --------
__device__ __align__(16) float  g_off  [Bn * 2 * CIN * HWd];   // offsets (B,2C,H,W) fp32
__device__ __align__(16) __half g_xt_hi[Bn * HWd * CIN];       // x pixel-major hi
__device__ __align__(16) __half g_xt_lo[Bn * HWd * CIN];       // x pixel-major lo
__device__ __align__(16) __half g_xd_hi[Bn * HWd * CIN];       // xdef pixel-major hi
__device__ __align__(16) __half g_xd_lo[Bn * HWd * CIN];       // xdef pixel-major lo
__device__ __align__(16) __half g_wa_hi[9 * 128 * CIN];        // W_off  (s,O,I) hi
__device__ __align__(16) __half g_wa_lo[9 * 128 * CIN];
__device__ __align__(16) __half g_wb_hi[9 *  64 * CIN];        // W_conv (s,O,I) hi
__device__ __align__(16) __half g_wb_lo[9 *  64 * CIN];

// ---------------- helpers ---------------------------------------------------
__device__ __forceinline__ uint32_t smem_u32(const void* p) {
    uint32_t a;
    asm("{ .reg .u64 t; cvta.to.shared.u64 t, %1; cvt.u32.u64 %0, t; }"
        : "=r"(a) : "l"(p));
    return a;
}
__device__ __forceinline__ void ldx4(uint32_t& r0, uint32_t& r1, uint32_t& r2,
                                     uint32_t& r3, uint32_t addr) {
    asm volatile("ldmatrix.sync.aligned.m8n8.x4.shared.b16 {%0,%1,%2,%3}, [%4];"
                 : "=r"(r0), "=r"(r1), "=r"(r2), "=r"(r3) : "r"(addr));
}
__device__ __forceinline__ void mma16816(float* d, const uint32_t* a,
                                         uint32_t b0, uint32_t b1) {
    asm volatile("mma.sync.aligned.m16n8k16.row.col.f32.f16.f16.f32 "
                 "{%0,%1,%2,%3}, {%4,%5,%6,%7}, {%8,%9}, {%0,%1,%2,%3};"
                 : "+f"(d[0]), "+f"(d[1]), "+f"(d[2]), "+f"(d[3])
                 : "r"(a[0]), "r"(a[1]), "r"(a[2]), "r"(a[3]), "r"(b0), "r"(b1));
}

// ---------------------------------------------------------------------------
// Transpose + fp16 hi/lo split: x (B,C,H,W) f32 -> (B,H,W,C) half hi + lo.
// ---------------------------------------------------------------------------
__global__ void __launch_bounds__(256)
xpose_split_kernel(const float* __restrict__ x, __half* __restrict__ hi, __half* __restrict__ lo)
{
    __shared__ float s[CIN][Wd + 1];
    const int tid = threadIdx.x;
    const int y = blockIdx.x & (Hd - 1);
    const int b = blockIdx.x >> 7;

    for (int idx = tid; idx < CIN * Wd; idx += 256) {
        const int c = idx >> 7, xx = idx & (Wd - 1);
        s[c][xx] = x[(((size_t)b * CIN + c) * Hd + y) * Wd + xx];
    }
    __syncthreads();
    for (int idx = tid; idx < Wd * (CIN / 2); idx += 256) {
        const int xx = idx >> 5, cp = idx & 31;
        const float v0 = s[2 * cp][xx], v1 = s[2 * cp + 1][xx];
        const __half h0 = __float2half_rn(v0), h1 = __float2half_rn(v1);
        const __half l0 = __float2half_rn(v0 - __half2float(h0));
        const __half l1 = __float2half_rn(v1 - __half2float(h1));
        const size_t base = ((size_t)(b * Hd + y) * Wd + xx) * CIN + 2 * cp;
        *reinterpret_cast<__half2*>(hi + base) = __halves2half2(h0, h1);
        *reinterpret_cast<__half2*>(lo + base) = __halves2half2(l0, l1);
    }
}

// ---------------------------------------------------------------------------
// Weight transform: W (O, CIN, 3, 3) f32 -> (s, O, CIN) half hi + lo.
// ---------------------------------------------------------------------------
__global__ void __launch_bounds__(256)
wsplit_kernel(const float* __restrict__ w, __half* __restrict__ hi, __half* __restrict__ lo, int O)
{
    const int idx = blockIdx.x * 256 + threadIdx.x;
    if (idx >= 9 * O * CIN) return;
    const int i = idx & (CIN - 1);
    const int o = (idx >> 6) % O;
    const int s = idx / (CIN * O);
    const float v = w[((size_t)o * CIN + i) * 9 + s];
    const __half h = __float2half_rn(v);
    hi[idx] = h;
    lo[idx] = __float2half_rn(v - __half2float(h));
}

// ---------------------------------------------------------------------------
// Implicit-GEMM 3x3 conv via mma.sync (HMMA, fp32 accum), fp16 hi/lo split.
// CTA = one (b, y) row: M=128 pixels, N=COUT. A staged per dy (130 shifted
// pixel rows), dx handled by re-indexing rows. B staged per shift.
// ---------------------------------------------------------------------------
template <int COUT, int WARPS_M, int WARPS_N>
__global__ void __launch_bounds__(256, 2)
conv_mma_kernel(const __half* __restrict__ a_hi, const __half* __restrict__ a_lo,
                const __half* __restrict__ w_hi, const __half* __restrict__ w_lo,
                const float* __restrict__ bias, float* __restrict__ out)
{
    constexpr int WM = 128 / WARPS_M;        // 64 or 32
    constexpr int WN = COUT / WARPS_N;       // 32
    constexpr int MF = WM / 16;              // 4 or 2
    constexpr int NF = WN / 8;               // 4
    constexpr int LDA = 72;                  // halves (144B rows: ldmatrix conflict-free)
    constexpr int LDB = 72;

    extern __shared__ char smem[];
    __half* sAh = reinterpret_cast<__half*>(smem);
    __half* sAl = sAh + 130 * LDA;
    __half* sBh = sAl + 130 * LDA;
    __half* sBl = sBh + COUT * LDB;
    float*  sEp = reinterpret_cast<float*>(smem);   // epilogue reuse: 32 x 132 f32

    const int tid  = threadIdx.x;
    const int lane = tid & 31, wid = tid >> 5;
    const int wm = wid % WARPS_M, wn = wid / WARPS_M;
    const int m0 = wm * WM, n0 = wn * WN;
    const int y = blockIdx.x & (Hd - 1);
    const int b = blockIdx.x >> 7;

    float d[MF][NF][4];
#pragma unroll
    for (int i = 0; i < MF; i++)
#pragma unroll
        for (int j = 0; j < NF; j++)
#pragma unroll
            for (int k = 0; k < 4; k++) d[i][j][k] = 0.0f;

    const uint32_t uAh = smem_u32(sAh), uAl = smem_u32(sAl);
    const uint32_t uBh = smem_u32(sBh), uBl = smem_u32(sBl);
    // per-thread ldmatrix address components
    const int a_row = lane & 15;
    const int a_k   = (lane >> 4) << 3;
    const int b_row = ((lane >> 4) << 3) + (lane & 7);
    const int b_k   = ((lane >> 3) & 1) << 3;

#pragma unroll 1
    for (int dy = 0; dy < 3; dy++) {
        const int yy = y + dy - 1;
        const bool rowok = (unsigned)yy < (unsigned)Hd;

#pragma unroll 1
        for (int dx = 0; dx < 3; dx++) {
            if (dx == 0) {
                // ---- stage A: 130 pixel rows (image x = p-1), 64 ch, hi+lo ----
                for (int idx = tid; idx < 130 * 16; idx += 256) {
                    const int p = idx >> 4, j = idx & 15;
                    const int xx = p - 1;
                    uint2 vh = make_uint2(0u, 0u), vl = make_uint2(0u, 0u);
                    if (rowok && (unsigned)xx < (unsigned)Wd) {
                        const size_t base = ((size_t)((b * Hd + yy) * Wd + xx)) * CIN + j * 4;
                        vh = *reinterpret_cast<const uint2*>(a_hi + base);
                        vl = *reinterpret_cast<const uint2*>(a_lo + base);
                    }
                    const int off = p * LDA + j * 4;
                    *reinterpret_cast<uint2*>(sAh + off) = vh;
                    *reinterpret_cast<uint2*>(sAl + off) = vl;
                }
            }
            // ---- stage B for shift s ----
            const int s = dy * 3 + dx;
            for (int idx = tid; idx < COUT * 16; idx += 256) {
                const int o = idx >> 4, j = idx & 15;
                const size_t base = ((size_t)(s * COUT + o)) * CIN + j * 4;
                const int off = o * LDB + j * 4;
                *reinterpret_cast<uint2*>(sBh + off) =
                    *reinterpret_cast<const uint2*>(w_hi + base);
                *reinterpret_cast<uint2*>(sBl + off) =
                    *reinterpret_cast<const uint2*>(w_lo + base);
            }
            __syncthreads();

            // ---- compute: K = 64 = 4 k-steps of 16 ----
#pragma unroll
            for (int kk = 0; kk < 4; kk++) {
                uint32_t ah[MF][4], al[MF][4];
#pragma unroll
                for (int mf = 0; mf < MF; mf++) {
                    const uint32_t off =
                        (uint32_t)((m0 + mf * 16 + a_row + dx) * LDA + kk * 16 + a_k) * 2;
                    ldx4(ah[mf][0], ah[mf][1], ah[mf][2], ah[mf][3], uAh + off);
                    ldx4(al[mf][0], al[mf][1], al[mf][2], al[mf][3], uAl + off);
                }
#pragma unroll
                for (int nfp = 0; nfp < NF / 2; nfp++) {
                    const uint32_t boff =
                        (uint32_t)((n0 + nfp * 16 + b_row) * LDB + kk * 16 + b_k) * 2;
                    uint32_t h0, h1, h2, h3, l0, l1, l2, l3;
                    ldx4(h0, h1, h2, h3, uBh + boff);
                    ldx4(l0, l1, l2, l3, uBl + boff);
#pragma unroll
                    for (int mf = 0; mf < MF; mf++) {
                        mma16816(d[mf][2 * nfp],     ah[mf], h0, h1);   // Ah*Bh
                        mma16816(d[mf][2 * nfp],     ah[mf], l0, l1);   // Ah*Bl
                        mma16816(d[mf][2 * nfp],     al[mf], h0, h1);   // Al*Bh
                        mma16816(d[mf][2 * nfp + 1], ah[mf], h2, h3);
                        mma16816(d[mf][2 * nfp + 1], ah[mf], l2, l3);
                        mma16816(d[mf][2 * nfp + 1], al[mf], h2, h3);
                    }
                }
            }
            __syncthreads();
        }
    }

    // ---- epilogue: chunks of 32 channels through smem, coalesced STG ----
#pragma unroll 1
    for (int nc = 0; nc < COUT; nc += 32) {
        if (n0 == nc) {
#pragma unroll
            for (int mf = 0; mf < MF; mf++) {
#pragma unroll
                for (int nf = 0; nf < NF; nf++) {
                    const int xl = m0 + mf * 16 + (lane >> 2);
                    const int c  = nf * 8 + (lane & 3) * 2;
                    sEp[ c      * 132 + xl    ] = d[mf][nf][0];
                    sEp[(c + 1) * 132 + xl    ] = d[mf][nf][1];
                    sEp[ c      * 132 + xl + 8] = d[mf][nf][2];
                    sEp[(c + 1) * 132 + xl + 8] = d[mf][nf][3];
                }
            }
        }
        __syncthreads();
        for (int idx = tid; idx < 32 * 128; idx += 256) {
            const int c = idx >> 7, q = idx & 127;
            float v = sEp[c * 132 + q];
            if (bias) v += __ldg(bias + nc + c);
            out[(((size_t)b * COUT + nc + c) * Hd + y) * Wd + q] = v;
        }
        __syncthreads();
    }
}

// ---------------------------------------------------------------------------
// Deformable gather -> pixel-major fp16 hi/lo (feeds conv B directly).
// ---------------------------------------------------------------------------
__global__ void __launch_bounds__(256)
gather_kernel(const float* __restrict__ x,       // (B, C, H, W)
              const float* __restrict__ off,     // (B, 2C, H, W)
              __half* __restrict__ xd_hi, __half* __restrict__ xd_lo)
{
    const int c = threadIdx.x;                       // 0..63
    const int p = blockIdx.x * 4 + threadIdx.y;      // 0..HW-1
    const int b = blockIdx.y;

    const int t   = 2 * p;
    const int ch  = 2 * c + (t >> 14);
    const int pos = t & (HWd - 1);
    const float2 o2 = *reinterpret_cast<const float2*>(
        off + ((size_t)b * (2 * CIN) + ch) * HWd + pos);

    const float gy = (float)(p >> 7);
    const float gx = (float)(p & 127);

    float cy = o2.x + gy;
    float cx = o2.y + gx;
    cy = fminf(fmaxf(cy, 0.0f), (float)(Hd - 1));
    cx = fminf(fmaxf(cx, 0.0f), (float)(Wd - 1));

    const float y0f = floorf(cy), y1f = ceilf(cy);
    const float x0f = floorf(cx), x1f = ceilf(cx);
    const int y0 = (int)y0f, y1 = (int)y1f;
    const int x0 = (int)x0f, x1 = (int)x1f;

    const float* xp = x + ((size_t)b * CIN + c) * HWd;
    const float v_lt = xp[y0 * Wd + x0];
    const float v_rb = xp[y1 * Wd + x1];
    const float v_lb = xp[y0 * Wd + x1];
    const float v_rt = xp[y1 * Wd + x0];

    const float dy = cy - y0f;
    const float dx = cx - x0f;
    const float v_t = dy * (v_rt - v_lt) + v_lt;
    const float v_b = dy * (v_rb - v_lb) + v_lb;
    const float res = dx * (v_b - v_t) + v_t;

    const __half h = __float2half_rn(res);
    const size_t o = ((size_t)b * HWd + p) * CIN + c;
    xd_hi[o] = h;
    xd_lo[o] = __float2half_rn(res - __half2float(h));
}

// ---------------------------------------------------------------------------
extern "C" void kernel_launch(void* const* d_in, const int* in_sizes, int n_in,
                              void* d_out, int out_size)
{
    const float* x      = (const float*)d_in[0];
    const float* W_off  = (const float*)d_in[1];
    const float* W_conv = (const float*)d_in[2];
    const float* b_conv = (const float*)d_in[3];
    float* out = (float*)d_out;

    float  *off_p;
    __half *xt_hi, *xt_lo, *xd_hi, *xd_lo, *wa_hi, *wa_lo, *wb_hi, *wb_lo;
    cudaGetSymbolAddress((void**)&off_p, g_off);
    cudaGetSymbolAddress((void**)&xt_hi, g_xt_hi);
    cudaGetSymbolAddress((void**)&xt_lo, g_xt_lo);
    cudaGetSymbolAddress((void**)&xd_hi, g_xd_hi);
    cudaGetSymbolAddress((void**)&xd_lo, g_xd_lo);
    cudaGetSymbolAddress((void**)&wa_hi, g_wa_hi);
    cudaGetSymbolAddress((void**)&wa_lo, g_wa_lo);
    cudaGetSymbolAddress((void**)&wb_hi, g_wb_hi);
    cudaGetSymbolAddress((void**)&wb_lo, g_wb_lo);

    // smem: A (2*130*72*2B) + B (COUT*72*2B*2)
    const int SMEM_A = 130 * 72 * 2 * 2 + 128 * 72 * 2 * 2;   // 74304
    const int SMEM_B = 130 * 72 * 2 * 2 +  64 * 72 * 2 * 2;   // 55872
    cudaFuncSetAttribute(conv_mma_kernel<128, 2, 4>,
                         cudaFuncAttributeMaxDynamicSharedMemorySize, SMEM_A);
    cudaFuncSetAttribute(conv_mma_kernel<64, 4, 2>,
                         cudaFuncAttributeMaxDynamicSharedMemorySize, SMEM_B);

    // 0) layout transforms
    xpose_split_kernel<<<Bn * Hd, 256>>>(x, xt_hi, xt_lo);
    wsplit_kernel<<<(9 * 128 * CIN + 255) / 256, 256>>>(W_off,  wa_hi, wa_lo, 128);
    wsplit_kernel<<<(9 *  64 * CIN + 255) / 256, 256>>>(W_conv, wb_hi, wb_lo, 64);

    // 1) offset conv (64 -> 128) on tensor pipe (HMMA)
    conv_mma_kernel<128, 2, 4><<<Bn * Hd, 256, SMEM_A>>>(
        xt_hi, xt_lo, wa_hi, wa_lo, nullptr, off_p);

    // 2) deformable bilinear gather -> fp16 hi/lo pixel-major
    gather_kernel<<<dim3(HWd / 4, Bn), dim3(64, 4)>>>(x, off_p, xd_hi, xd_lo);

    // 3) main conv (64 -> 64) + bias on tensor pipe (HMMA)
    conv_mma_kernel<64, 4, 2><<<Bn * Hd, 256, SMEM_B>>>(
        xd_hi, xd_lo, wb_hi, wb_lo, b_conv, out);
}

// round 8
// speedup vs baseline: 2.3426x; 1.0875x over previous
#include <cuda_runtime.h>
#include <cuda_fp16.h>
#include <cstdint>

#define Hd   128
#define Wd   128
#define CIN  64
#define HWd  (Hd * Wd)
#define Bn   8

// ---------------- scratch (device globals; allocation is forbidden) --------
__device__ __align__(16) float  g_off  [Bn * 2 * CIN * HWd];   // offsets (B,2C,H,W) fp32
__device__ __align__(16) __half g_xt_hi[Bn * HWd * CIN];       // x pixel-major hi
__device__ __align__(16) __half g_xt_lo[Bn * HWd * CIN];       // x pixel-major lo
__device__ __align__(16) __half g_xd_hi[Bn * HWd * CIN];       // xdef pixel-major hi
__device__ __align__(16) __half g_xd_lo[Bn * HWd * CIN];       // xdef pixel-major lo
__device__ __align__(16) __half g_wa_hi[9 * 128 * CIN];        // W_off  (s,O,I) hi
__device__ __align__(16) __half g_wa_lo[9 * 128 * CIN];
__device__ __align__(16) __half g_wb_hi[9 *  64 * CIN];        // W_conv (s,O,I) hi
__device__ __align__(16) __half g_wb_lo[9 *  64 * CIN];

// ---------------- helpers ---------------------------------------------------
__device__ __forceinline__ uint32_t smem_u32(const void* p) {
    uint32_t a;
    asm("{ .reg .u64 t; cvta.to.shared.u64 t, %1; cvt.u32.u64 %0, t; }"
        : "=r"(a) : "l"(p));
    return a;
}
__device__ __forceinline__ void ldx4(uint32_t& r0, uint32_t& r1, uint32_t& r2,
                                     uint32_t& r3, uint32_t addr) {
    asm volatile("ldmatrix.sync.aligned.m8n8.x4.shared.b16 {%0,%1,%2,%3}, [%4];"
                 : "=r"(r0), "=r"(r1), "=r"(r2), "=r"(r3) : "r"(addr));
}
__device__ __forceinline__ void mma16816(float* d, const uint32_t* a,
                                         uint32_t b0, uint32_t b1) {
    asm volatile("mma.sync.aligned.m16n8k16.row.col.f32.f16.f16.f32 "
                 "{%0,%1,%2,%3}, {%4,%5,%6,%7}, {%8,%9}, {%0,%1,%2,%3};"
                 : "+f"(d[0]), "+f"(d[1]), "+f"(d[2]), "+f"(d[3])
                 : "r"(a[0]), "r"(a[1]), "r"(a[2]), "r"(a[3]), "r"(b0), "r"(b1));
}
// cp.async 16B with zero-fill when pred==false (src still a valid address)
__device__ __forceinline__ void cpa16(uint32_t dst, const void* src, bool pred) {
    asm volatile("cp.async.cg.shared.global [%0], [%1], 16, %2;"
                 :: "r"(dst), "l"(src), "r"(pred ? 16u : 0u));
}
#define CP_COMMIT()  asm volatile("cp.async.commit_group;" ::: "memory")
#define CP_WAIT1()   asm volatile("cp.async.wait_group 1;" ::: "memory")

// ---------------------------------------------------------------------------
// Transpose + fp16 hi/lo split: x (B,C,H,W) f32 -> (B,H,W,C) half hi + lo.
// ---------------------------------------------------------------------------
__global__ void __launch_bounds__(256)
xpose_split_kernel(const float* __restrict__ x, __half* __restrict__ hi, __half* __restrict__ lo)
{
    __shared__ float s[CIN][Wd + 1];
    const int tid = threadIdx.x;
    const int y = blockIdx.x & (Hd - 1);
    const int b = blockIdx.x >> 7;

    for (int idx = tid; idx < CIN * Wd; idx += 256) {
        const int c = idx >> 7, xx = idx & (Wd - 1);
        s[c][xx] = x[(((size_t)b * CIN + c) * Hd + y) * Wd + xx];
    }
    __syncthreads();
    for (int idx = tid; idx < Wd * (CIN / 2); idx += 256) {
        const int xx = idx >> 5, cp = idx & 31;
        const float v0 = s[2 * cp][xx], v1 = s[2 * cp + 1][xx];
        const __half h0 = __float2half_rn(v0), h1 = __float2half_rn(v1);
        const __half l0 = __float2half_rn(v0 - __half2float(h0));
        const __half l1 = __float2half_rn(v1 - __half2float(h1));
        const size_t base = ((size_t)(b * Hd + y) * Wd + xx) * CIN + 2 * cp;
        *reinterpret_cast<__half2*>(hi + base) = __halves2half2(h0, h1);
        *reinterpret_cast<__half2*>(lo + base) = __halves2half2(l0, l1);
    }
}

// ---------------------------------------------------------------------------
// Weight transform: W (O, CIN, 3, 3) f32 -> (s, O, CIN) half hi + lo.
// ---------------------------------------------------------------------------
__global__ void __launch_bounds__(256)
wsplit_kernel(const float* __restrict__ w, __half* __restrict__ hi, __half* __restrict__ lo, int O)
{
    const int idx = blockIdx.x * 256 + threadIdx.x;
    if (idx >= 9 * O * CIN) return;
    const int i = idx & (CIN - 1);
    const int o = (idx >> 6) % O;
    const int s = idx / (CIN * O);
    const float v = w[((size_t)o * CIN + i) * 9 + s];
    const __half h = __float2half_rn(v);
    hi[idx] = h;
    lo[idx] = __float2half_rn(v - __half2float(h));
}

// ---------------------------------------------------------------------------
// Implicit-GEMM 3x3 conv via mma.sync (HMMA, fp32 accum), fp16 hi/lo split,
// cp.async double-buffered pipeline (A per-dy, B per-shift).
// CTA = one (b, y) row: M=128 pixels, N=COUT.
// ---------------------------------------------------------------------------
template <int COUT, int WARPS_M, int WARPS_N>
__global__ void __launch_bounds__(256)
conv_mma_kernel(const __half* __restrict__ a_hi, const __half* __restrict__ a_lo,
                const __half* __restrict__ w_hi, const __half* __restrict__ w_lo,
                const float* __restrict__ bias, float* __restrict__ out)
{
    constexpr int WM = 128 / WARPS_M;
    constexpr int WN = COUT / WARPS_N;
    constexpr int MF = WM / 16;
    constexpr int NF = WN / 8;
    constexpr int LDA = 72;                  // 144B rows: ldmatrix conflict-free
    constexpr int LDB = 72;
    constexpr int ASEG = 130 * LDA;          // halves per A component
    constexpr int BSEG = COUT * LDB;         // halves per B component
    constexpr int BOFF = 4 * ASEG;           // halves offset of B region

    extern __shared__ __align__(16) __half smem[];
    const uint32_t sb = smem_u32(smem);

    const int tid  = threadIdx.x;
    const int lane = tid & 31, wid = tid >> 5;
    const int wm = wid % WARPS_M, wn = wid / WARPS_M;
    const int m0 = wm * WM, n0 = wn * WN;
    const int y = blockIdx.x & (Hd - 1);
    const int b = blockIdx.x >> 7;

    // ---- staging helpers (cp.async 16B) ----
    auto stageA = [&](int buf, int dy) {
        const int yy = y + dy - 1;
        const bool rowok = (unsigned)yy < (unsigned)Hd;
        const uint32_t dh = sb + (uint32_t)(buf * 2 * ASEG) * 2;
        const uint32_t dl = dh + ASEG * 2;
        for (int idx = tid; idx < 130 * 8; idx += 256) {
            const int p = idx >> 3, j = idx & 7;
            const int xx = p - 1;
            const bool ok = rowok && (unsigned)xx < (unsigned)Wd;
            const size_t base = ok ? (((size_t)((b * Hd + yy) * Wd + xx)) * CIN + j * 8) : 0;
            const uint32_t doff = (uint32_t)(p * LDA + j * 8) * 2;
            cpa16(dh + doff, a_hi + base, ok);
            cpa16(dl + doff, a_lo + base, ok);
        }
    };
    auto stageB = [&](int buf, int s) {
        const uint32_t dh = sb + (uint32_t)(BOFF + buf * 2 * BSEG) * 2;
        const uint32_t dl = dh + BSEG * 2;
        for (int idx = tid; idx < COUT * 8; idx += 256) {
            const int o = idx >> 3, j = idx & 7;
            const size_t base = ((size_t)(s * COUT + o)) * CIN + j * 8;
            const uint32_t doff = (uint32_t)(o * LDB + j * 8) * 2;
            cpa16(dh + doff, w_hi + base, true);
            cpa16(dl + doff, w_lo + base, true);
        }
    };

    float d[MF][NF][4];
#pragma unroll
    for (int i = 0; i < MF; i++)
#pragma unroll
        for (int j = 0; j < NF; j++)
#pragma unroll
            for (int k = 0; k < 4; k++) d[i][j][k] = 0.0f;

    // ldmatrix per-thread address components
    const int a_row = lane & 15;
    const int a_k   = (lane >> 4) << 3;
    const int b_row = ((lane >> 4) << 3) + (lane & 7);
    const int b_k   = ((lane >> 3) & 1) << 3;

    // ---- prologue: two groups in flight ----
    stageA(0, 0); stageB(0, 0); CP_COMMIT();
    stageA(1, 1); stageB(1, 1); CP_COMMIT();

#pragma unroll 1
    for (int s = 0; s < 9; s++) {
        const int dy = s / 3, dx = s % 3;
        const int abuf = dy & 1, bbuf = s & 1;

        CP_WAIT1();
        __syncthreads();

        const uint32_t uAh = sb + (uint32_t)(abuf * 2 * ASEG) * 2;
        const uint32_t uAl = uAh + ASEG * 2;
        const uint32_t uBh = sb + (uint32_t)(BOFF + bbuf * 2 * BSEG) * 2;
        const uint32_t uBl = uBh + BSEG * 2;

#pragma unroll
        for (int kk = 0; kk < 4; kk++) {
            uint32_t ah[MF][4], al[MF][4];
#pragma unroll
            for (int mf = 0; mf < MF; mf++) {
                const uint32_t off =
                    (uint32_t)((m0 + mf * 16 + a_row + dx) * LDA + kk * 16 + a_k) * 2;
                ldx4(ah[mf][0], ah[mf][1], ah[mf][2], ah[mf][3], uAh + off);
                ldx4(al[mf][0], al[mf][1], al[mf][2], al[mf][3], uAl + off);
            }
#pragma unroll
            for (int nfp = 0; nfp < NF / 2; nfp++) {
                const uint32_t boff =
                    (uint32_t)((n0 + nfp * 16 + b_row) * LDB + kk * 16 + b_k) * 2;
                uint32_t h0, h1, h2, h3, l0, l1, l2, l3;
                ldx4(h0, h1, h2, h3, uBh + boff);
                ldx4(l0, l1, l2, l3, uBl + boff);
#pragma unroll
                for (int mf = 0; mf < MF; mf++) {
                    mma16816(d[mf][2 * nfp],     ah[mf], h0, h1);   // Ah*Bh
                    mma16816(d[mf][2 * nfp],     ah[mf], l0, l1);   // Ah*Bl
                    mma16816(d[mf][2 * nfp],     al[mf], h0, h1);   // Al*Bh
                    mma16816(d[mf][2 * nfp + 1], ah[mf], h2, h3);
                    mma16816(d[mf][2 * nfp + 1], ah[mf], l2, l3);
                    mma16816(d[mf][2 * nfp + 1], al[mf], h2, h3);
                }
            }
        }
        __syncthreads();   // all warps done reading buffers

        // ---- prefetch shift s+2 into the now-free buffers ----
        if (s + 2 <= 8) {
            if ((s + 2) % 3 == 0) stageA(((s + 2) / 3) & 1, (s + 2) / 3);
            stageB((s + 2) & 1, s + 2);
        }
        CP_COMMIT();
    }

    // ---- single-pass epilogue through smem, coalesced STG ----
    float* sEp = reinterpret_cast<float*>(smem);   // COUT x 132
#pragma unroll
    for (int mf = 0; mf < MF; mf++) {
#pragma unroll
        for (int nf = 0; nf < NF; nf++) {
            const int xl = m0 + mf * 16 + (lane >> 2);
            const int c  = n0 + nf * 8 + (lane & 3) * 2;
            sEp[ c      * 132 + xl    ] = d[mf][nf][0];
            sEp[(c + 1) * 132 + xl    ] = d[mf][nf][1];
            sEp[ c      * 132 + xl + 8] = d[mf][nf][2];
            sEp[(c + 1) * 132 + xl + 8] = d[mf][nf][3];
        }
    }
    __syncthreads();
    for (int idx = tid; idx < COUT * 128; idx += 256) {
        const int c = idx >> 7, q = idx & 127;
        float v = sEp[c * 132 + q];
        if (bias) v += __ldg(bias + c);
        out[(((size_t)b * COUT + c) * Hd + y) * Wd + q] = v;
    }
}

// ---------------------------------------------------------------------------
// Plane-local deformable gather -> pixel-major fp16 hi/lo.
// Block = 256 consecutive pixels of one batch; loop over 64 channels
// (corner reads stay inside one 64KB channel plane -> sector locality).
// Results transposed through smem into coalesced pixel-major writes.
// ---------------------------------------------------------------------------
__global__ void __launch_bounds__(256)
gather_kernel(const float* __restrict__ x,       // (B, C, H, W)
              const float* __restrict__ off,     // (B, 2C, H, W)
              __half* __restrict__ xd_hi, __half* __restrict__ xd_lo)
{
    constexpr int LDC = 68;                       // halves; [p][c] stride
    extern __shared__ __align__(16) __half gsm[]; // s_hi[256][68], s_lo[256][68]
    __half* s_hi = gsm;
    __half* s_lo = gsm + 256 * LDC;

    const int t  = threadIdx.x;
    const int p0 = blockIdx.x * 256;
    const int b  = blockIdx.y;
    const int p  = p0 + t;

    const float gy = (float)(p >> 7);
    const float gx = (float)(p & 127);
    const int   t2 = 2 * p;
    const int   chb = t2 >> 14;                   // 0 or 1
    const int   pos = t2 & (HWd - 1);
    const float* offb = off + (size_t)b * (2 * CIN) * HWd + pos;
    const float* xb   = x + (size_t)b * CIN * HWd;

#pragma unroll 1
    for (int c = 0; c < CIN; c++) {
        const float2 o2 = *reinterpret_cast<const float2*>(
            offb + (size_t)(2 * c + chb) * HWd);

        float cy = o2.x + gy;
        float cx = o2.y + gx;
        cy = fminf(fmaxf(cy, 0.0f), (float)(Hd - 1));
        cx = fminf(fmaxf(cx, 0.0f), (float)(Wd - 1));

        const float y0f = floorf(cy), y1f = ceilf(cy);
        const float x0f = floorf(cx), x1f = ceilf(cx);
        const int y0 = (int)y0f, y1 = (int)y1f;
        const int x0 = (int)x0f, x1 = (int)x1f;

        const float* xp = xb + (size_t)c * HWd;
        const float v_lt = xp[y0 * Wd + x0];
        const float v_rb = xp[y1 * Wd + x1];
        const float v_lb = xp[y0 * Wd + x1];
        const float v_rt = xp[y1 * Wd + x0];

        const float dyf = cy - y0f;
        const float dxf = cx - x0f;
        const float v_t = dyf * (v_rt - v_lt) + v_lt;
        const float v_b = dyf * (v_rb - v_lb) + v_lb;
        const float res = dxf * (v_b - v_t) + v_t;

        const __half h = __float2half_rn(res);
        s_hi[t * LDC + c] = h;
        s_lo[t * LDC + c] = __float2half_rn(res - __half2float(h));
    }
    __syncthreads();

    // coalesced pixel-major writes: per pixel 64 ch = 128B (hi) + 128B (lo)
    for (int idx = t; idx < 256 * 16; idx += 256) {
        const int pp = idx >> 4, j = idx & 15;
        const uint2 vh = *reinterpret_cast<const uint2*>(s_hi + pp * LDC + j * 4);
        const uint2 vl = *reinterpret_cast<const uint2*>(s_lo + pp * LDC + j * 4);
        const size_t o = ((size_t)b * HWd + p0 + pp) * CIN + j * 4;
        *reinterpret_cast<uint2*>(xd_hi + o) = vh;
        *reinterpret_cast<uint2*>(xd_lo + o) = vl;
    }
}

// ---------------------------------------------------------------------------
extern "C" void kernel_launch(void* const* d_in, const int* in_sizes, int n_in,
                              void* d_out, int out_size)
{
    const float* x      = (const float*)d_in[0];
    const float* W_off  = (const float*)d_in[1];
    const float* W_conv = (const float*)d_in[2];
    const float* b_conv = (const float*)d_in[3];
    float* out = (float*)d_out;

    float  *off_p;
    __half *xt_hi, *xt_lo, *xd_hi, *xd_lo, *wa_hi, *wa_lo, *wb_hi, *wb_lo;
    cudaGetSymbolAddress((void**)&off_p, g_off);
    cudaGetSymbolAddress((void**)&xt_hi, g_xt_hi);
    cudaGetSymbolAddress((void**)&xt_lo, g_xt_lo);
    cudaGetSymbolAddress((void**)&xd_hi, g_xd_hi);
    cudaGetSymbolAddress((void**)&xd_lo, g_xd_lo);
    cudaGetSymbolAddress((void**)&wa_hi, g_wa_hi);
    cudaGetSymbolAddress((void**)&wa_lo, g_wa_lo);
    cudaGetSymbolAddress((void**)&wb_hi, g_wb_hi);
    cudaGetSymbolAddress((void**)&wb_lo, g_wb_lo);

    // dynamic smem: 4 A bufs (130*72) + 4 B bufs (COUT*72), halves
    const int SMEM_A = (4 * 130 * 72 + 4 * 128 * 72) * 2;   // 148608
    const int SMEM_B = (4 * 130 * 72 + 4 *  64 * 72) * 2;   // 111744
    const int SMEM_G = 2 * 256 * 68 * 2;                    // 69632
    cudaFuncSetAttribute(conv_mma_kernel<128, 2, 4>,
                         cudaFuncAttributeMaxDynamicSharedMemorySize, SMEM_A);
    cudaFuncSetAttribute(conv_mma_kernel<64, 4, 2>,
                         cudaFuncAttributeMaxDynamicSharedMemorySize, SMEM_B);
    cudaFuncSetAttribute(gather_kernel,
                         cudaFuncAttributeMaxDynamicSharedMemorySize, SMEM_G);

    // 0) layout transforms
    xpose_split_kernel<<<Bn * Hd, 256>>>(x, xt_hi, xt_lo);
    wsplit_kernel<<<(9 * 128 * CIN + 255) / 256, 256>>>(W_off,  wa_hi, wa_lo, 128);
    wsplit_kernel<<<(9 *  64 * CIN + 255) / 256, 256>>>(W_conv, wb_hi, wb_lo, 64);

    // 1) offset conv (64 -> 128) on tensor pipe (HMMA, pipelined)
    conv_mma_kernel<128, 2, 4><<<Bn * Hd, 256, SMEM_A>>>(
        xt_hi, xt_lo, wa_hi, wa_lo, nullptr, off_p);

    // 2) plane-local deformable gather -> fp16 hi/lo pixel-major
    gather_kernel<<<dim3(HWd / 256, Bn), 256, SMEM_G>>>(x, off_p, xd_hi, xd_lo);

    // 3) main conv (64 -> 64) + bias on tensor pipe (HMMA, pipelined)
    conv_mma_kernel<64, 4, 2><<<Bn * Hd, 256, SMEM_B>>>(
        xd_hi, xd_lo, wb_hi, wb_lo, b_conv, out);
}

// round 9
// speedup vs baseline: 3.2109x; 1.3706x over previous
#include <cuda_runtime.h>
#include <cuda_fp16.h>
#include <cstdint>

#define Hd   128
#define Wd   128
#define CIN  64
#define HWd  (Hd * Wd)
#define Bn   8

// ---------------- scratch (device globals; allocation is forbidden) --------
__device__ __align__(16) float  g_off  [Bn * 2 * CIN * HWd];   // offsets (B,2C,H,W) fp32
__device__ __align__(16) __half g_xt_hi[Bn * HWd * CIN];       // x pixel-major fp16
__device__ __align__(16) __half g_xd_hi[Bn * HWd * CIN];       // xdef pixel-major hi
__device__ __align__(16) __half g_xd_lo[Bn * HWd * CIN];       // xdef pixel-major lo
__device__ __align__(16) __half g_wa_hi[9 * 128 * CIN];        // W_off  (s,O,I) fp16
__device__ __align__(16) __half g_wb_hi[9 *  64 * CIN];        // W_conv (s,O,I) hi
__device__ __align__(16) __half g_wb_lo[9 *  64 * CIN];        // W_conv (s,O,I) lo

// ---------------- helpers ---------------------------------------------------
__device__ __forceinline__ uint32_t smem_u32(const void* p) {
    uint32_t a;
    asm("{ .reg .u64 t; cvta.to.shared.u64 t, %1; cvt.u32.u64 %0, t; }"
        : "=r"(a) : "l"(p));
    return a;
}
__device__ __forceinline__ void ldx4(uint32_t& r0, uint32_t& r1, uint32_t& r2,
                                     uint32_t& r3, uint32_t addr) {
    asm volatile("ldmatrix.sync.aligned.m8n8.x4.shared.b16 {%0,%1,%2,%3}, [%4];"
                 : "=r"(r0), "=r"(r1), "=r"(r2), "=r"(r3) : "r"(addr));
}
__device__ __forceinline__ void mma16816(float* d, const uint32_t* a,
                                         uint32_t b0, uint32_t b1) {
    asm volatile("mma.sync.aligned.m16n8k16.row.col.f32.f16.f16.f32 "
                 "{%0,%1,%2,%3}, {%4,%5,%6,%7}, {%8,%9}, {%0,%1,%2,%3};"
                 : "+f"(d[0]), "+f"(d[1]), "+f"(d[2]), "+f"(d[3])
                 : "r"(a[0]), "r"(a[1]), "r"(a[2]), "r"(a[3]), "r"(b0), "r"(b1));
}
// cp.async 16B with zero-fill when pred==false (src still a valid address)
__device__ __forceinline__ void cpa16(uint32_t dst, const void* src, bool pred) {
    asm volatile("cp.async.cg.shared.global [%0], [%1], 16, %2;"
                 :: "r"(dst), "l"(src), "r"(pred ? 16u : 0u));
}
#define CP_COMMIT()  asm volatile("cp.async.commit_group;" ::: "memory")
#define CP_WAIT1()   asm volatile("cp.async.wait_group 1;" ::: "memory")

// ---------------------------------------------------------------------------
// Transpose to pixel-major fp16: x (B,C,H,W) f32 -> (B,H,W,C) half.
// ---------------------------------------------------------------------------
__global__ void __launch_bounds__(256)
xpose_kernel(const float* __restrict__ x, __half* __restrict__ hi)
{
    __shared__ float s[CIN][Wd + 1];
    const int tid = threadIdx.x;
    const int y = blockIdx.x & (Hd - 1);
    const int b = blockIdx.x >> 7;

    for (int idx = tid; idx < CIN * Wd; idx += 256) {
        const int c = idx >> 7, xx = idx & (Wd - 1);
        s[c][xx] = x[(((size_t)b * CIN + c) * Hd + y) * Wd + xx];
    }
    __syncthreads();
    for (int idx = tid; idx < Wd * (CIN / 2); idx += 256) {
        const int xx = idx >> 5, cp = idx & 31;
        const __half h0 = __float2half_rn(s[2 * cp][xx]);
        const __half h1 = __float2half_rn(s[2 * cp + 1][xx]);
        const size_t base = ((size_t)(b * Hd + y) * Wd + xx) * CIN + 2 * cp;
        *reinterpret_cast<__half2*>(hi + base) = __halves2half2(h0, h1);
    }
}

// ---------------------------------------------------------------------------
// Weight transform: W (O, CIN, 3, 3) f32 -> (s, O, CIN) half hi (+ lo if given).
// ---------------------------------------------------------------------------
__global__ void __launch_bounds__(256)
wsplit_kernel(const float* __restrict__ w, __half* __restrict__ hi,
              __half* __restrict__ lo, int O)
{
    const int idx = blockIdx.x * 256 + threadIdx.x;
    if (idx >= 9 * O * CIN) return;
    const int i = idx & (CIN - 1);
    const int o = (idx >> 6) % O;
    const int s = idx / (CIN * O);
    const float v = w[((size_t)o * CIN + i) * 9 + s];
    const __half h = __float2half_rn(v);
    hi[idx] = h;
    if (lo) lo[idx] = __float2half_rn(v - __half2float(h));
}

// ---------------------------------------------------------------------------
// Implicit-GEMM 3x3 conv via mma.sync (HMMA, fp32 accum), cp.async pipeline.
// SPLIT=true: fp16 hi/lo 3-product (near-fp32). SPLIT=false: plain fp16.
// CTA = one (b, y) row: M=128 pixels, N=COUT.
// ---------------------------------------------------------------------------
template <int COUT, int WARPS_M, int WARPS_N, bool SPLIT>
__global__ void __launch_bounds__(256)
conv_mma_kernel(const __half* __restrict__ a_hi, const __half* __restrict__ a_lo,
                const __half* __restrict__ w_hi, const __half* __restrict__ w_lo,
                const float* __restrict__ bias, float* __restrict__ out)
{
    constexpr int COMPS = SPLIT ? 2 : 1;
    constexpr int WM = 128 / WARPS_M;
    constexpr int WN = COUT / WARPS_N;
    constexpr int MF = WM / 16;
    constexpr int NF = WN / 8;
    constexpr int LDA = 72;                  // 144B rows: ldmatrix conflict-free
    constexpr int LDB = 72;
    constexpr int ASEG = 130 * LDA;          // halves per A component buffer
    constexpr int BSEG = COUT * LDB;         // halves per B component buffer
    constexpr int BOFF = 2 * COMPS * ASEG;   // halves offset of B region

    extern __shared__ __align__(16) __half smem[];
    const uint32_t sb = smem_u32(smem);

    const int tid  = threadIdx.x;
    const int lane = tid & 31, wid = tid >> 5;
    const int wm = wid % WARPS_M, wn = wid / WARPS_M;
    const int m0 = wm * WM, n0 = wn * WN;
    const int y = blockIdx.x & (Hd - 1);
    const int b = blockIdx.x >> 7;

    auto stageA = [&](int buf, int dy) {
        const int yy = y + dy - 1;
        const bool rowok = (unsigned)yy < (unsigned)Hd;
        const uint32_t dh = sb + (uint32_t)(buf * COMPS * ASEG) * 2;
        for (int idx = tid; idx < 130 * 8; idx += 256) {
            const int p = idx >> 3, j = idx & 7;
            const int xx = p - 1;
            const bool ok = rowok && (unsigned)xx < (unsigned)Wd;
            const size_t base = ok ? (((size_t)((b * Hd + yy) * Wd + xx)) * CIN + j * 8) : 0;
            const uint32_t doff = (uint32_t)(p * LDA + j * 8) * 2;
            cpa16(dh + doff, a_hi + base, ok);
            if (SPLIT) cpa16(dh + ASEG * 2 + doff, a_lo + base, ok);
        }
    };
    auto stageB = [&](int buf, int s) {
        const uint32_t dh = sb + (uint32_t)(BOFF + buf * COMPS * BSEG) * 2;
        for (int idx = tid; idx < COUT * 8; idx += 256) {
            const int o = idx >> 3, j = idx & 7;
            const size_t base = ((size_t)(s * COUT + o)) * CIN + j * 8;
            const uint32_t doff = (uint32_t)(o * LDB + j * 8) * 2;
            cpa16(dh + doff, w_hi + base, true);
            if (SPLIT) cpa16(dh + BSEG * 2 + doff, w_lo + base, true);
        }
    };

    float d[MF][NF][4];
#pragma unroll
    for (int i = 0; i < MF; i++)
#pragma unroll
        for (int j = 0; j < NF; j++)
#pragma unroll
            for (int k = 0; k < 4; k++) d[i][j][k] = 0.0f;

    const int a_row = lane & 15;
    const int a_k   = (lane >> 4) << 3;
    const int b_row = ((lane >> 4) << 3) + (lane & 7);
    const int b_k   = ((lane >> 3) & 1) << 3;

    // ---- prologue: two groups in flight ----
    stageA(0, 0); stageB(0, 0); CP_COMMIT();
    stageA(1, 1); stageB(1, 1); CP_COMMIT();

#pragma unroll 1
    for (int s = 0; s < 9; s++) {
        const int dy = s / 3, dx = s % 3;
        const int abuf = dy & 1, bbuf = s & 1;

        CP_WAIT1();
        __syncthreads();

        const uint32_t uAh = sb + (uint32_t)(abuf * COMPS * ASEG) * 2;
        const uint32_t uAl = uAh + ASEG * 2;
        const uint32_t uBh = sb + (uint32_t)(BOFF + bbuf * COMPS * BSEG) * 2;
        const uint32_t uBl = uBh + BSEG * 2;

#pragma unroll
        for (int kk = 0; kk < 4; kk++) {
            uint32_t ah[MF][4], al[MF][4];
#pragma unroll
            for (int mf = 0; mf < MF; mf++) {
                const uint32_t off =
                    (uint32_t)((m0 + mf * 16 + a_row + dx) * LDA + kk * 16 + a_k) * 2;
                ldx4(ah[mf][0], ah[mf][1], ah[mf][2], ah[mf][3], uAh + off);
                if (SPLIT) ldx4(al[mf][0], al[mf][1], al[mf][2], al[mf][3], uAl + off);
            }
#pragma unroll
            for (int nfp = 0; nfp < NF / 2; nfp++) {
                const uint32_t boff =
                    (uint32_t)((n0 + nfp * 16 + b_row) * LDB + kk * 16 + b_k) * 2;
                uint32_t h0, h1, h2, h3;
                ldx4(h0, h1, h2, h3, uBh + boff);
#pragma unroll
                for (int mf = 0; mf < MF; mf++) {
                    mma16816(d[mf][2 * nfp],     ah[mf], h0, h1);
                    mma16816(d[mf][2 * nfp + 1], ah[mf], h2, h3);
                }
                if (SPLIT) {
                    uint32_t l0, l1, l2, l3;
                    ldx4(l0, l1, l2, l3, uBl + boff);
#pragma unroll
                    for (int mf = 0; mf < MF; mf++) {
                        mma16816(d[mf][2 * nfp],     ah[mf], l0, l1);   // Ah*Bl
                        mma16816(d[mf][2 * nfp],     al[mf], h0, h1);   // Al*Bh
                        mma16816(d[mf][2 * nfp + 1], ah[mf], l2, l3);
                        mma16816(d[mf][2 * nfp + 1], al[mf], h2, h3);
                    }
                }
            }
        }
        __syncthreads();   // all warps done reading buffers

        // ---- prefetch shift s+2 (A only needed once more: dy=2 into buf 0) ----
        if (s + 2 <= 8) {
            if (s + 2 == 6) stageA(0, 2);
            stageB((s + 2) & 1, s + 2);
        }
        CP_COMMIT();
    }

    // ---- single-pass epilogue through smem, coalesced STG ----
    float* sEp = reinterpret_cast<float*>(smem);   // COUT x 132
#pragma unroll
    for (int mf = 0; mf < MF; mf++) {
#pragma unroll
        for (int nf = 0; nf < NF; nf++) {
            const int xl = m0 + mf * 16 + (lane >> 2);
            const int c  = n0 + nf * 8 + (lane & 3) * 2;
            sEp[ c      * 132 + xl    ] = d[mf][nf][0];
            sEp[(c + 1) * 132 + xl    ] = d[mf][nf][1];
            sEp[ c      * 132 + xl + 8] = d[mf][nf][2];
            sEp[(c + 1) * 132 + xl + 8] = d[mf][nf][3];
        }
    }
    __syncthreads();
    for (int idx = tid; idx < COUT * 128; idx += 256) {
        const int c = idx >> 7, q = idx & 127;
        float v = sEp[c * 132 + q];
        if (bias) v += __ldg(bias + c);
        out[(((size_t)b * COUT + c) * Hd + y) * Wd + q] = v;
    }
}

// ---------------------------------------------------------------------------
// Plane-local deformable gather -> pixel-major fp16 hi/lo.
// Block = 256 consecutive pixels; loop over channels (sector locality).
// ---------------------------------------------------------------------------
__global__ void __launch_bounds__(256)
gather_kernel(const float* __restrict__ x,       // (B, C, H, W)
              const float* __restrict__ off,     // (B, 2C, H, W)
              __half* __restrict__ xd_hi, __half* __restrict__ xd_lo)
{
    constexpr int LDC = 68;
    extern __shared__ __align__(16) __half gsm[]; // s_hi[256][68], s_lo[256][68]
    __half* s_hi = gsm;
    __half* s_lo = gsm + 256 * LDC;

    const int t  = threadIdx.x;
    const int p0 = blockIdx.x * 256;
    const int b  = blockIdx.y;
    const int p  = p0 + t;

    const float gy = (float)(p >> 7);
    const float gx = (float)(p & 127);
    const int   t2 = 2 * p;
    const int   chb = t2 >> 14;
    const int   pos = t2 & (HWd - 1);
    const float* offb = off + (size_t)b * (2 * CIN) * HWd + pos;
    const float* xb   = x + (size_t)b * CIN * HWd;

#pragma unroll 1
    for (int c = 0; c < CIN; c++) {
        const float2 o2 = *reinterpret_cast<const float2*>(
            offb + (size_t)(2 * c + chb) * HWd);

        float cy = o2.x + gy;
        float cx = o2.y + gx;
        cy = fminf(fmaxf(cy, 0.0f), (float)(Hd - 1));
        cx = fminf(fmaxf(cx, 0.0f), (float)(Wd - 1));

        const float y0f = floorf(cy), y1f = ceilf(cy);
        const float x0f = floorf(cx), x1f = ceilf(cx);
        const int y0 = (int)y0f, y1 = (int)y1f;
        const int x0 = (int)x0f, x1 = (int)x1f;

        const float* xp = xb + (size_t)c * HWd;
        const float v_lt = xp[y0 * Wd + x0];
        const float v_rb = xp[y1 * Wd + x1];
        const float v_lb = xp[y0 * Wd + x1];
        const float v_rt = xp[y1 * Wd + x0];

        const float dyf = cy - y0f;
        const float dxf = cx - x0f;
        const float v_t = dyf * (v_rt - v_lt) + v_lt;
        const float v_b = dyf * (v_rb - v_lb) + v_lb;
        const float res = dxf * (v_b - v_t) + v_t;

        const __half h = __float2half_rn(res);
        s_hi[t * LDC + c] = h;
        s_lo[t * LDC + c] = __float2half_rn(res - __half2float(h));
    }
    __syncthreads();

    for (int idx = t; idx < 256 * 16; idx += 256) {
        const int pp = idx >> 4, j = idx & 15;
        const uint2 vh = *reinterpret_cast<const uint2*>(s_hi + pp * LDC + j * 4);
        const uint2 vl = *reinterpret_cast<const uint2*>(s_lo + pp * LDC + j * 4);
        const size_t o = ((size_t)b * HWd + p0 + pp) * CIN + j * 4;
        *reinterpret_cast<uint2*>(xd_hi + o) = vh;
        *reinterpret_cast<uint2*>(xd_lo + o) = vl;
    }
}

// ---------------------------------------------------------------------------
extern "C" void kernel_launch(void* const* d_in, const int* in_sizes, int n_in,
                              void* d_out, int out_size)
{
    const float* x      = (const float*)d_in[0];
    const float* W_off  = (const float*)d_in[1];
    const float* W_conv = (const float*)d_in[2];
    const float* b_conv = (const float*)d_in[3];
    float* out = (float*)d_out;

    float  *off_p;
    __half *xt_hi, *xd_hi, *xd_lo, *wa_hi, *wb_hi, *wb_lo;
    cudaGetSymbolAddress((void**)&off_p, g_off);
    cudaGetSymbolAddress((void**)&xt_hi, g_xt_hi);
    cudaGetSymbolAddress((void**)&xd_hi, g_xd_hi);
    cudaGetSymbolAddress((void**)&xd_lo, g_xd_lo);
    cudaGetSymbolAddress((void**)&wa_hi, g_wa_hi);
    cudaGetSymbolAddress((void**)&wb_hi, g_wb_hi);
    cudaGetSymbolAddress((void**)&wb_lo, g_wb_lo);

    // smem: A bufs + B bufs (halves)
    const int SMEM_A = (2 * 130 * 72 + 2 * 128 * 72) * 2;   // 74304  (fp16, COMPS=1)
    const int SMEM_B = (4 * 130 * 72 + 4 *  64 * 72) * 2;   // 111744 (split, COMPS=2)
    const int SMEM_G = 2 * 256 * 68 * 2;                    // 69632
    cudaFuncSetAttribute((conv_mma_kernel<128, 2, 4, false>),
                         cudaFuncAttributeMaxDynamicSharedMemorySize, SMEM_A);
    cudaFuncSetAttribute((conv_mma_kernel<64, 4, 2, true>),
                         cudaFuncAttributeMaxDynamicSharedMemorySize, SMEM_B);
    cudaFuncSetAttribute(gather_kernel,
                         cudaFuncAttributeMaxDynamicSharedMemorySize, SMEM_G);

    // 0) layout transforms
    xpose_kernel<<<Bn * Hd, 256>>>(x, xt_hi);
    wsplit_kernel<<<(9 * 128 * CIN + 255) / 256, 256>>>(W_off,  wa_hi, nullptr, 128);
    wsplit_kernel<<<(9 *  64 * CIN + 255) / 256, 256>>>(W_conv, wb_hi, wb_lo, 64);

    // 1) offset conv (64 -> 128), plain fp16 single product (precision slack)
    conv_mma_kernel<128, 2, 4, false><<<Bn * Hd, 256, SMEM_A>>>(
        xt_hi, nullptr, wa_hi, nullptr, nullptr, off_p);

    // 2) plane-local deformable gather -> fp16 hi/lo pixel-major
    gather_kernel<<<dim3(HWd / 256, Bn), 256, SMEM_G>>>(x, off_p, xd_hi, xd_lo);

    // 3) main conv (64 -> 64) + bias, hi/lo 3-product (near-fp32)
    conv_mma_kernel<64, 4, 2, true><<<Bn * Hd, 256, SMEM_B>>>(
        xd_hi, xd_lo, wb_hi, wb_lo, b_conv, out);
}

// round 10
// speedup vs baseline: 3.4761x; 1.0826x over previous
#include <cuda_runtime.h>
#include <cuda_fp16.h>
#include <cstdint>

#define Hd   128
#define Wd   128
#define CIN  64
#define HWd  (Hd * Wd)
#define Bn   8

// ---------------- scratch (device globals; allocation is forbidden) --------
__device__ __align__(16) float  g_off  [Bn * 2 * CIN * HWd];   // offsets (B,2C,H,W) fp32
__device__ __align__(16) __half g_xt_hi[Bn * HWd * CIN];       // x pixel-major fp16
__device__ __align__(16) __half g_xd_hi[Bn * HWd * CIN];       // xdef pixel-major hi
__device__ __align__(16) __half g_xd_lo[Bn * HWd * CIN];       // xdef pixel-major lo
__device__ __align__(16) __half g_wa_hi[9 * 128 * CIN];        // W_off  (s,O,I) fp16
__device__ __align__(16) __half g_wb_hi[9 *  64 * CIN];        // W_conv (s,O,I) fp16

// ---------------- helpers ---------------------------------------------------
__device__ __forceinline__ uint32_t smem_u32(const void* p) {
    uint32_t a;
    asm("{ .reg .u64 t; cvta.to.shared.u64 t, %1; cvt.u32.u64 %0, t; }"
        : "=r"(a) : "l"(p));
    return a;
}
__device__ __forceinline__ void ldx4(uint32_t& r0, uint32_t& r1, uint32_t& r2,
                                     uint32_t& r3, uint32_t addr) {
    asm volatile("ldmatrix.sync.aligned.m8n8.x4.shared.b16 {%0,%1,%2,%3}, [%4];"
                 : "=r"(r0), "=r"(r1), "=r"(r2), "=r"(r3) : "r"(addr));
}
__device__ __forceinline__ void mma16816(float* d, const uint32_t* a,
                                         uint32_t b0, uint32_t b1) {
    asm volatile("mma.sync.aligned.m16n8k16.row.col.f32.f16.f16.f32 "
                 "{%0,%1,%2,%3}, {%4,%5,%6,%7}, {%8,%9}, {%0,%1,%2,%3};"
                 : "+f"(d[0]), "+f"(d[1]), "+f"(d[2]), "+f"(d[3])
                 : "r"(a[0]), "r"(a[1]), "r"(a[2]), "r"(a[3]), "r"(b0), "r"(b1));
}
// cp.async 16B with zero-fill when pred==false (src still a valid address)
__device__ __forceinline__ void cpa16(uint32_t dst, const void* src, bool pred) {
    asm volatile("cp.async.cg.shared.global [%0], [%1], 16, %2;"
                 :: "r"(dst), "l"(src), "r"(pred ? 16u : 0u));
}
#define CP_COMMIT()  asm volatile("cp.async.commit_group;" ::: "memory")
#define CP_WAIT1()   asm volatile("cp.async.wait_group 1;" ::: "memory")

// ---------------------------------------------------------------------------
// Transpose to pixel-major fp16: x (B,C,H,W) f32 -> (B,H,W,C) half.
// ---------------------------------------------------------------------------
__global__ void __launch_bounds__(256)
xpose_kernel(const float* __restrict__ x, __half* __restrict__ hi)
{
    __shared__ float s[CIN][Wd + 1];
    const int tid = threadIdx.x;
    const int y = blockIdx.x & (Hd - 1);
    const int b = blockIdx.x >> 7;

    for (int idx = tid; idx < CIN * Wd; idx += 256) {
        const int c = idx >> 7, xx = idx & (Wd - 1);
        s[c][xx] = x[(((size_t)b * CIN + c) * Hd + y) * Wd + xx];
    }
    __syncthreads();
    for (int idx = tid; idx < Wd * (CIN / 2); idx += 256) {
        const int xx = idx >> 5, cp = idx & 31;
        const __half h0 = __float2half_rn(s[2 * cp][xx]);
        const __half h1 = __float2half_rn(s[2 * cp + 1][xx]);
        const size_t base = ((size_t)(b * Hd + y) * Wd + xx) * CIN + 2 * cp;
        *reinterpret_cast<__half2*>(hi + base) = __halves2half2(h0, h1);
    }
}

// ---------------------------------------------------------------------------
// Weight transform: W (O, CIN, 3, 3) f32 -> (s, O, CIN) fp16.
// ---------------------------------------------------------------------------
__global__ void __launch_bounds__(256)
wsplit_kernel(const float* __restrict__ w, __half* __restrict__ hi, int O)
{
    const int idx = blockIdx.x * 256 + threadIdx.x;
    if (idx >= 9 * O * CIN) return;
    const int i = idx & (CIN - 1);
    const int o = (idx >> 6) % O;
    const int s = idx / (CIN * O);
    hi[idx] = __float2half_rn(w[((size_t)o * CIN + i) * 9 + s]);
}

// ---------------------------------------------------------------------------
// Implicit-GEMM 3x3 conv via mma.sync (HMMA, fp32 accum), cp.async pipeline.
// ASPLIT=true: A in fp16 hi/lo (2 products, 22-bit A); B always plain fp16.
// CTA = one (b, y) row: M=128 pixels, N=COUT.
// ---------------------------------------------------------------------------
template <int COUT, int WARPS_M, int WARPS_N, bool ASPLIT>
__global__ void __launch_bounds__(256)
conv_mma_kernel(const __half* __restrict__ a_hi, const __half* __restrict__ a_lo,
                const __half* __restrict__ w_hi,
                const float* __restrict__ bias, float* __restrict__ out)
{
    constexpr int COMPS = ASPLIT ? 2 : 1;
    constexpr int WM = 128 / WARPS_M;
    constexpr int WN = COUT / WARPS_N;
    constexpr int MF = WM / 16;
    constexpr int NF = WN / 8;
    constexpr int LDA = 72;                  // 144B rows: ldmatrix conflict-free
    constexpr int LDB = 72;
    constexpr int ASEG = 130 * LDA;          // halves per A component buffer
    constexpr int BSEG = COUT * LDB;         // halves per B buffer
    constexpr int BOFF = 2 * COMPS * ASEG;   // halves offset of B region

    extern __shared__ __align__(16) __half smem[];
    const uint32_t sb = smem_u32(smem);

    const int tid  = threadIdx.x;
    const int lane = tid & 31, wid = tid >> 5;
    const int wm = wid % WARPS_M, wn = wid / WARPS_M;
    const int m0 = wm * WM, n0 = wn * WN;
    const int y = blockIdx.x & (Hd - 1);
    const int b = blockIdx.x >> 7;

    auto stageA = [&](int buf, int dy) {
        const int yy = y + dy - 1;
        const bool rowok = (unsigned)yy < (unsigned)Hd;
        const uint32_t dh = sb + (uint32_t)(buf * COMPS * ASEG) * 2;
        for (int idx = tid; idx < 130 * 8; idx += 256) {
            const int p = idx >> 3, j = idx & 7;
            const int xx = p - 1;
            const bool ok = rowok && (unsigned)xx < (unsigned)Wd;
            const size_t base = ok ? (((size_t)((b * Hd + yy) * Wd + xx)) * CIN + j * 8) : 0;
            const uint32_t doff = (uint32_t)(p * LDA + j * 8) * 2;
            cpa16(dh + doff, a_hi + base, ok);
            if (ASPLIT) cpa16(dh + ASEG * 2 + doff, a_lo + base, ok);
        }
    };
    auto stageB = [&](int buf, int s) {
        const uint32_t dh = sb + (uint32_t)(BOFF + buf * BSEG) * 2;
        for (int idx = tid; idx < COUT * 8; idx += 256) {
            const int o = idx >> 3, j = idx & 7;
            const size_t base = ((size_t)(s * COUT + o)) * CIN + j * 8;
            const uint32_t doff = (uint32_t)(o * LDB + j * 8) * 2;
            cpa16(dh + doff, w_hi + base, true);
        }
    };

    float d[MF][NF][4];
#pragma unroll
    for (int i = 0; i < MF; i++)
#pragma unroll
        for (int j = 0; j < NF; j++)
#pragma unroll
            for (int k = 0; k < 4; k++) d[i][j][k] = 0.0f;

    const int a_row = lane & 15;
    const int a_k   = (lane >> 4) << 3;
    const int b_row = ((lane >> 4) << 3) + (lane & 7);
    const int b_k   = ((lane >> 3) & 1) << 3;

    // ---- prologue: two groups in flight ----
    stageA(0, 0); stageB(0, 0); CP_COMMIT();
    stageA(1, 1); stageB(1, 1); CP_COMMIT();

#pragma unroll 1
    for (int s = 0; s < 9; s++) {
        const int dy = s / 3, dx = s % 3;
        const int abuf = dy & 1, bbuf = s & 1;

        CP_WAIT1();
        __syncthreads();

        const uint32_t uAh = sb + (uint32_t)(abuf * COMPS * ASEG) * 2;
        const uint32_t uAl = uAh + ASEG * 2;
        const uint32_t uBh = sb + (uint32_t)(BOFF + bbuf * BSEG) * 2;

#pragma unroll
        for (int kk = 0; kk < 4; kk++) {
            uint32_t ah[MF][4], al[MF][4];
#pragma unroll
            for (int mf = 0; mf < MF; mf++) {
                const uint32_t off =
                    (uint32_t)((m0 + mf * 16 + a_row + dx) * LDA + kk * 16 + a_k) * 2;
                ldx4(ah[mf][0], ah[mf][1], ah[mf][2], ah[mf][3], uAh + off);
                if (ASPLIT) ldx4(al[mf][0], al[mf][1], al[mf][2], al[mf][3], uAl + off);
            }
#pragma unroll
            for (int nfp = 0; nfp < NF / 2; nfp++) {
                const uint32_t boff =
                    (uint32_t)((n0 + nfp * 16 + b_row) * LDB + kk * 16 + b_k) * 2;
                uint32_t h0, h1, h2, h3;
                ldx4(h0, h1, h2, h3, uBh + boff);
#pragma unroll
                for (int mf = 0; mf < MF; mf++) {
                    mma16816(d[mf][2 * nfp],     ah[mf], h0, h1);
                    mma16816(d[mf][2 * nfp + 1], ah[mf], h2, h3);
                    if (ASPLIT) {
                        mma16816(d[mf][2 * nfp],     al[mf], h0, h1);   // Al*Bh
                        mma16816(d[mf][2 * nfp + 1], al[mf], h2, h3);
                    }
                }
            }
        }
        __syncthreads();   // all warps done reading buffers

        // ---- prefetch shift s+2 (A only needed once more: dy=2 into buf 0) ----
        if (s + 2 <= 8) {
            if (s + 2 == 6) stageA(0, 2);
            stageB((s + 2) & 1, s + 2);
        }
        CP_COMMIT();
    }

    // ---- single-pass epilogue through smem, coalesced STG ----
    float* sEp = reinterpret_cast<float*>(smem);   // COUT x 132
#pragma unroll
    for (int mf = 0; mf < MF; mf++) {
#pragma unroll
        for (int nf = 0; nf < NF; nf++) {
            const int xl = m0 + mf * 16 + (lane >> 2);
            const int c  = n0 + nf * 8 + (lane & 3) * 2;
            sEp[ c      * 132 + xl    ] = d[mf][nf][0];
            sEp[(c + 1) * 132 + xl    ] = d[mf][nf][1];
            sEp[ c      * 132 + xl + 8] = d[mf][nf][2];
            sEp[(c + 1) * 132 + xl + 8] = d[mf][nf][3];
        }
    }
    __syncthreads();
    for (int idx = tid; idx < COUT * 128; idx += 256) {
        const int c = idx >> 7, q = idx & 127;
        float v = sEp[c * 132 + q];
        if (bias) v += __ldg(bias + c);
        out[(((size_t)b * COUT + c) * Hd + y) * Wd + q] = v;
    }
}

// ---------------------------------------------------------------------------
// Plane-local deformable gather -> pixel-major fp16 hi/lo.
// Block = 256 consecutive pixels; loop over channels (sector locality).
// ---------------------------------------------------------------------------
__global__ void __launch_bounds__(256)
gather_kernel(const float* __restrict__ x,       // (B, C, H, W)
              const float* __restrict__ off,     // (B, 2C, H, W)
              __half* __restrict__ xd_hi, __half* __restrict__ xd_lo)
{
    constexpr int LDC = 68;
    extern __shared__ __align__(16) __half gsm[]; // s_hi[256][68], s_lo[256][68]
    __half* s_hi = gsm;
    __half* s_lo = gsm + 256 * LDC;

    const int t  = threadIdx.x;
    const int p0 = blockIdx.x * 256;
    const int b  = blockIdx.y;
    const int p  = p0 + t;

    const float gy = (float)(p >> 7);
    const float gx = (float)(p & 127);
    const int   t2 = 2 * p;
    const int   chb = t2 >> 14;
    const int   pos = t2 & (HWd - 1);
    const float* offb = off + (size_t)b * (2 * CIN) * HWd + pos;
    const float* xb   = x + (size_t)b * CIN * HWd;

#pragma unroll 1
    for (int c = 0; c < CIN; c++) {
        const float2 o2 = *reinterpret_cast<const float2*>(
            offb + (size_t)(2 * c + chb) * HWd);

        float cy = o2.x + gy;
        float cx = o2.y + gx;
        cy = fminf(fmaxf(cy, 0.0f), (float)(Hd - 1));
        cx = fminf(fmaxf(cx, 0.0f), (float)(Wd - 1));

        const float y0f = floorf(cy), y1f = ceilf(cy);
        const float x0f = floorf(cx), x1f = ceilf(cx);
        const int y0 = (int)y0f, y1 = (int)y1f;
        const int x0 = (int)x0f, x1 = (int)x1f;

        const float* xp = xb + (size_t)c * HWd;
        const float v_lt = xp[y0 * Wd + x0];
        const float v_rb = xp[y1 * Wd + x1];
        const float v_lb = xp[y0 * Wd + x1];
        const float v_rt = xp[y1 * Wd + x0];

        const float dyf = cy - y0f;
        const float dxf = cx - x0f;
        const float v_t = dyf * (v_rt - v_lt) + v_lt;
        const float v_b = dyf * (v_rb - v_lb) + v_lb;
        const float res = dxf * (v_b - v_t) + v_t;

        const __half h = __float2half_rn(res);
        s_hi[t * LDC + c] = h;
        s_lo[t * LDC + c] = __float2half_rn(res - __half2float(h));
    }
    __syncthreads();

    for (int idx = t; idx < 256 * 16; idx += 256) {
        const int pp = idx >> 4, j = idx & 15;
        const uint2 vh = *reinterpret_cast<const uint2*>(s_hi + pp * LDC + j * 4);
        const uint2 vl = *reinterpret_cast<const uint2*>(s_lo + pp * LDC + j * 4);
        const size_t o = ((size_t)b * HWd + p0 + pp) * CIN + j * 4;
        *reinterpret_cast<uint2*>(xd_hi + o) = vh;
        *reinterpret_cast<uint2*>(xd_lo + o) = vl;
    }
}

// ---------------------------------------------------------------------------
extern "C" void kernel_launch(void* const* d_in, const int* in_sizes, int n_in,
                              void* d_out, int out_size)
{
    const float* x      = (const float*)d_in[0];
    const float* W_off  = (const float*)d_in[1];
    const float* W_conv = (const float*)d_in[2];
    const float* b_conv = (const float*)d_in[3];
    float* out = (float*)d_out;

    float  *off_p;
    __half *xt_hi, *xd_hi, *xd_lo, *wa_hi, *wb_hi;
    cudaGetSymbolAddress((void**)&off_p, g_off);
    cudaGetSymbolAddress((void**)&xt_hi, g_xt_hi);
    cudaGetSymbolAddress((void**)&xd_hi, g_xd_hi);
    cudaGetSymbolAddress((void**)&xd_lo, g_xd_lo);
    cudaGetSymbolAddress((void**)&wa_hi, g_wa_hi);
    cudaGetSymbolAddress((void**)&wb_hi, g_wb_hi);

    // smem: A bufs + B bufs (halves)
    const int SMEM_A = (2 * 130 * 72 + 2 * 128 * 72) * 2;   // 74304 (COMPS=1)
    const int SMEM_B = (4 * 130 * 72 + 2 *  64 * 72) * 2;   // 93312 (COMPS=2, B hi only)
    const int SMEM_G = 2 * 256 * 68 * 2;                    // 69632
    cudaFuncSetAttribute((conv_mma_kernel<128, 2, 4, false>),
                         cudaFuncAttributeMaxDynamicSharedMemorySize, SMEM_A);
    cudaFuncSetAttribute((conv_mma_kernel<64, 4, 2, true>),
                         cudaFuncAttributeMaxDynamicSharedMemorySize, SMEM_B);
    cudaFuncSetAttribute(gather_kernel,
                         cudaFuncAttributeMaxDynamicSharedMemorySize, SMEM_G);

    // 0) layout transforms
    xpose_kernel<<<Bn * Hd, 256>>>(x, xt_hi);
    wsplit_kernel<<<(9 * 128 * CIN + 255) / 256, 256>>>(W_off,  wa_hi, 128);
    wsplit_kernel<<<(9 *  64 * CIN + 255) / 256, 256>>>(W_conv, wb_hi, 64);

    // 1) offset conv (64 -> 128), plain fp16 single product (precision slack)
    conv_mma_kernel<128, 2, 4, false><<<Bn * Hd, 256, SMEM_A>>>(
        xt_hi, nullptr, wa_hi, nullptr, off_p);

    // 2) plane-local deformable gather -> fp16 hi/lo pixel-major
    gather_kernel<<<dim3(HWd / 256, Bn), 256, SMEM_G>>>(x, off_p, xd_hi, xd_lo);

    // 3) main conv (64 -> 64) + bias, A hi/lo 2-product (22-bit A, fp16 W)
    conv_mma_kernel<64, 4, 2, true><<<Bn * Hd, 256, SMEM_B>>>(
        xd_hi, xd_lo, wb_hi, b_conv, out);
}

// round 11
// speedup vs baseline: 3.4775x; 1.0004x over previous
#include <cuda_runtime.h>
#include <cuda_fp16.h>
#include <cstdint>

#define Hd   128
#define Wd   128
#define CIN  64
#define HWd  (Hd * Wd)
#define Bn   8

// ---------------- scratch (device globals; allocation is forbidden) --------
__device__ __align__(16) float  g_off  [Bn * 2 * CIN * HWd];   // offsets (B,2C,H,W) fp32
__device__ __align__(16) __half g_xt_hi[Bn * HWd * CIN];       // x pixel-major fp16
__device__ __align__(16) __half g_xd_hi[Bn * HWd * CIN];       // xdef pixel-major hi
__device__ __align__(16) __half g_xd_lo[Bn * HWd * CIN];       // xdef pixel-major lo
__device__ __align__(16) __half g_wa_hi[9 * 128 * CIN];        // W_off  (s,O,I) fp16
__device__ __align__(16) __half g_wb_hi[9 *  64 * CIN];        // W_conv (s,O,I) fp16

// ---------------- helpers ---------------------------------------------------
__device__ __forceinline__ uint32_t smem_u32(const void* p) {
    uint32_t a;
    asm("{ .reg .u64 t; cvta.to.shared.u64 t, %1; cvt.u32.u64 %0, t; }"
        : "=r"(a) : "l"(p));
    return a;
}
__device__ __forceinline__ void ldx4(uint32_t& r0, uint32_t& r1, uint32_t& r2,
                                     uint32_t& r3, uint32_t addr) {
    asm volatile("ldmatrix.sync.aligned.m8n8.x4.shared.b16 {%0,%1,%2,%3}, [%4];"
                 : "=r"(r0), "=r"(r1), "=r"(r2), "=r"(r3) : "r"(addr));
}
__device__ __forceinline__ void mma16816(float* d, const uint32_t* a,
                                         uint32_t b0, uint32_t b1) {
    asm volatile("mma.sync.aligned.m16n8k16.row.col.f32.f16.f16.f32 "
                 "{%0,%1,%2,%3}, {%4,%5,%6,%7}, {%8,%9}, {%0,%1,%2,%3};"
                 : "+f"(d[0]), "+f"(d[1]), "+f"(d[2]), "+f"(d[3])
                 : "r"(a[0]), "r"(a[1]), "r"(a[2]), "r"(a[3]), "r"(b0), "r"(b1));
}
// cp.async 16B with zero-fill when pred==false (src still a valid address)
__device__ __forceinline__ void cpa16(uint32_t dst, const void* src, bool pred) {
    asm volatile("cp.async.cg.shared.global [%0], [%1], 16, %2;"
                 :: "r"(dst), "l"(src), "r"(pred ? 16u : 0u));
}
#define CP_COMMIT()  asm volatile("cp.async.commit_group;" ::: "memory")
#define CP_WAIT0()   asm volatile("cp.async.wait_group 0;" ::: "memory")

// ---------------------------------------------------------------------------
// Transpose to pixel-major fp16: x (B,C,H,W) f32 -> (B,H,W,C) half.
// ---------------------------------------------------------------------------
__global__ void __launch_bounds__(256)
xpose_kernel(const float* __restrict__ x, __half* __restrict__ hi)
{
    __shared__ float s[CIN][Wd + 1];
    const int tid = threadIdx.x;
    const int y = blockIdx.x & (Hd - 1);
    const int b = blockIdx.x >> 7;

    for (int idx = tid; idx < CIN * Wd; idx += 256) {
        const int c = idx >> 7, xx = idx & (Wd - 1);
        s[c][xx] = x[(((size_t)b * CIN + c) * Hd + y) * Wd + xx];
    }
    __syncthreads();
    for (int idx = tid; idx < Wd * (CIN / 2); idx += 256) {
        const int xx = idx >> 5, cp = idx & 31;
        const __half h0 = __float2half_rn(s[2 * cp][xx]);
        const __half h1 = __float2half_rn(s[2 * cp + 1][xx]);
        const size_t base = ((size_t)(b * Hd + y) * Wd + xx) * CIN + 2 * cp;
        *reinterpret_cast<__half2*>(hi + base) = __halves2half2(h0, h1);
    }
}

// ---------------------------------------------------------------------------
// Weight transform: W (O, CIN, 3, 3) f32 -> (s, O, CIN) fp16.
// ---------------------------------------------------------------------------
__global__ void __launch_bounds__(256)
wsplit_kernel(const float* __restrict__ w, __half* __restrict__ hi, int O)
{
    const int idx = blockIdx.x * 256 + threadIdx.x;
    if (idx >= 9 * O * CIN) return;
    const int i = idx & (CIN - 1);
    const int o = (idx >> 6) % O;
    const int s = idx / (CIN * O);
    hi[idx] = __float2half_rn(w[((size_t)o * CIN + i) * 9 + s]);
}

// ---------------------------------------------------------------------------
// Implicit-GEMM 3x3 conv via mma.sync (HMMA, fp32 accum), dy-outer pipeline:
// A per-dy double-buffered (cp.async), B staged for ALL 3 dx shifts of a dy
// at once (single-buffered) -> 2 barriers per dy (6 total, was 18).
// ASPLIT=true: A in fp16 hi/lo (2 products, 22-bit A); B plain fp16.
// CTA = one (b, y) row: M=128 pixels, N=COUT.
// ---------------------------------------------------------------------------
template <int COUT, int WARPS_M, int WARPS_N, bool ASPLIT>
__global__ void __launch_bounds__(256)
conv_mma_kernel(const __half* __restrict__ a_hi, const __half* __restrict__ a_lo,
                const __half* __restrict__ w_hi,
                const float* __restrict__ bias, float* __restrict__ out)
{
    constexpr int COMPS = ASPLIT ? 2 : 1;
    constexpr int WM = 128 / WARPS_M;
    constexpr int WN = COUT / WARPS_N;
    constexpr int MF = WM / 16;
    constexpr int NF = WN / 8;
    constexpr int LDA = 72;                  // 144B rows: ldmatrix conflict-free
    constexpr int LDB = 72;
    constexpr int ASEG = 130 * LDA;          // halves per A component buffer
    constexpr int BSEG = COUT * LDB;         // halves per B shift slot
    constexpr int BOFF = 2 * COMPS * ASEG;   // halves offset of B region (3 slots)

    extern __shared__ __align__(16) __half smem[];
    const uint32_t sb = smem_u32(smem);

    const int tid  = threadIdx.x;
    const int lane = tid & 31, wid = tid >> 5;
    const int wm = wid % WARPS_M, wn = wid / WARPS_M;
    const int m0 = wm * WM, n0 = wn * WN;
    const int y = blockIdx.x & (Hd - 1);
    const int b = blockIdx.x >> 7;

    auto stageA = [&](int buf, int dy) {
        const int yy = y + dy - 1;
        const bool rowok = (unsigned)yy < (unsigned)Hd;
        const uint32_t dh = sb + (uint32_t)(buf * COMPS * ASEG) * 2;
        for (int idx = tid; idx < 130 * 8; idx += 256) {
            const int p = idx >> 3, j = idx & 7;
            const int xx = p - 1;
            const bool ok = rowok && (unsigned)xx < (unsigned)Wd;
            const size_t base = ok ? (((size_t)((b * Hd + yy) * Wd + xx)) * CIN + j * 8) : 0;
            const uint32_t doff = (uint32_t)(p * LDA + j * 8) * 2;
            cpa16(dh + doff, a_hi + base, ok);
            if (ASPLIT) cpa16(dh + ASEG * 2 + doff, a_lo + base, ok);
        }
    };
    // stage B for all 3 dx shifts of row-group dy: [dx][COUT][LDB]
    auto stageB3 = [&](int dy) {
        const int s0 = dy * 3;
        const uint32_t dh = sb + (uint32_t)BOFF * 2;
        for (int idx = tid; idx < 3 * COUT * 8; idx += 256) {
            const int op = idx >> 3, j = idx & 7;      // op = dx*COUT + o
            const size_t base = ((size_t)(s0 * COUT) + op) * CIN + j * 8;
            const uint32_t doff = (uint32_t)(op * LDB + j * 8) * 2;
            cpa16(dh + doff, w_hi + base, true);
        }
    };

    float d[MF][NF][4];
#pragma unroll
    for (int i = 0; i < MF; i++)
#pragma unroll
        for (int j = 0; j < NF; j++)
#pragma unroll
            for (int k = 0; k < 4; k++) d[i][j][k] = 0.0f;

    const int a_row = lane & 15;
    const int a_k   = (lane >> 4) << 3;
    const int b_row = ((lane >> 4) << 3) + (lane & 7);
    const int b_k   = ((lane >> 3) & 1) << 3;

    // ---- prologue: A(dy0), A(dy1), B(dy0) in one group ----
    stageA(0, 0); stageA(1, 1); stageB3(0); CP_COMMIT();

#pragma unroll 1
    for (int dy = 0; dy < 3; dy++) {
        CP_WAIT0();
        __syncthreads();

        const uint32_t uAh = sb + (uint32_t)((dy & 1) * COMPS * ASEG) * 2;
        const uint32_t uAl = uAh + ASEG * 2;

#pragma unroll 1
        for (int dx = 0; dx < 3; dx++) {
            const uint32_t uB = sb + (uint32_t)(BOFF + dx * BSEG) * 2;
#pragma unroll
            for (int kk = 0; kk < 4; kk++) {
                uint32_t ah[MF][4], al[MF][4];
#pragma unroll
                for (int mf = 0; mf < MF; mf++) {
                    const uint32_t off =
                        (uint32_t)((m0 + mf * 16 + a_row + dx) * LDA + kk * 16 + a_k) * 2;
                    ldx4(ah[mf][0], ah[mf][1], ah[mf][2], ah[mf][3], uAh + off);
                    if (ASPLIT) ldx4(al[mf][0], al[mf][1], al[mf][2], al[mf][3], uAl + off);
                }
#pragma unroll
                for (int nfp = 0; nfp < NF / 2; nfp++) {
                    const uint32_t boff =
                        (uint32_t)((n0 + nfp * 16 + b_row) * LDB + kk * 16 + b_k) * 2;
                    uint32_t h0, h1, h2, h3;
                    ldx4(h0, h1, h2, h3, uB + boff);
#pragma unroll
                    for (int mf = 0; mf < MF; mf++) {
                        mma16816(d[mf][2 * nfp],     ah[mf], h0, h1);
                        mma16816(d[mf][2 * nfp + 1], ah[mf], h2, h3);
                        if (ASPLIT) {
                            mma16816(d[mf][2 * nfp],     al[mf], h0, h1);   // Al*Bh
                            mma16816(d[mf][2 * nfp + 1], al[mf], h2, h3);
                        }
                    }
                }
            }
        }
        __syncthreads();   // B slots + A buffer free to restage

        if (dy < 2) {
            if (dy == 0) stageA(0, 2);   // A(dy2) into buf 0
            stageB3(dy + 1);
        }
        CP_COMMIT();
    }

    // ---- single-pass epilogue through smem, coalesced STG ----
    float* sEp = reinterpret_cast<float*>(smem);   // COUT x 132
#pragma unroll
    for (int mf = 0; mf < MF; mf++) {
#pragma unroll
        for (int nf = 0; nf < NF; nf++) {
            const int xl = m0 + mf * 16 + (lane >> 2);
            const int c  = n0 + nf * 8 + (lane & 3) * 2;
            sEp[ c      * 132 + xl    ] = d[mf][nf][0];
            sEp[(c + 1) * 132 + xl    ] = d[mf][nf][1];
            sEp[ c      * 132 + xl + 8] = d[mf][nf][2];
            sEp[(c + 1) * 132 + xl + 8] = d[mf][nf][3];
        }
    }
    __syncthreads();
    for (int idx = tid; idx < COUT * 128; idx += 256) {
        const int c = idx >> 7, q = idx & 127;
        float v = sEp[c * 132 + q];
        if (bias) v += __ldg(bias + c);
        out[(((size_t)b * COUT + c) * Hd + y) * Wd + q] = v;
    }
}

// ---------------------------------------------------------------------------
// Plane-local deformable gather -> pixel-major fp16 hi/lo.
// Block = 256 consecutive pixels; loop over channels (sector locality).
// ---------------------------------------------------------------------------
__global__ void __launch_bounds__(256)
gather_kernel(const float* __restrict__ x,       // (B, C, H, W)
              const float* __restrict__ off,     // (B, 2C, H, W)
              __half* __restrict__ xd_hi, __half* __restrict__ xd_lo)
{
    constexpr int LDC = 68;
    extern __shared__ __align__(16) __half gsm[]; // s_hi[256][68], s_lo[256][68]
    __half* s_hi = gsm;
    __half* s_lo = gsm + 256 * LDC;

    const int t  = threadIdx.x;
    const int p0 = blockIdx.x * 256;
    const int b  = blockIdx.y;
    const int p  = p0 + t;

    const float gy = (float)(p >> 7);
    const float gx = (float)(p & 127);
    const int   t2 = 2 * p;
    const int   chb = t2 >> 14;
    const int   pos = t2 & (HWd - 1);
    const float* offb = off + (size_t)b * (2 * CIN) * HWd + pos;
    const float* xb   = x + (size_t)b * CIN * HWd;

#pragma unroll 1
    for (int c = 0; c < CIN; c++) {
        const float2 o2 = *reinterpret_cast<const float2*>(
            offb + (size_t)(2 * c + chb) * HWd);

        float cy = o2.x + gy;
        float cx = o2.y + gx;
        cy = fminf(fmaxf(cy, 0.0f), (float)(Hd - 1));
        cx = fminf(fmaxf(cx, 0.0f), (float)(Wd - 1));

        const float y0f = floorf(cy), y1f = ceilf(cy);
        const float x0f = floorf(cx), x1f = ceilf(cx);
        const int y0 = (int)y0f, y1 = (int)y1f;
        const int x0 = (int)x0f, x1 = (int)x1f;

        const float* xp = xb + (size_t)c * HWd;
        const float v_lt = xp[y0 * Wd + x0];
        const float v_rb = xp[y1 * Wd + x1];
        const float v_lb = xp[y0 * Wd + x1];
        const float v_rt = xp[y1 * Wd + x0];

        const float dyf = cy - y0f;
        const float dxf = cx - x0f;
        const float v_t = dyf * (v_rt - v_lt) + v_lt;
        const float v_b = dyf * (v_rb - v_lb) + v_lb;
        const float res = dxf * (v_b - v_t) + v_t;

        const __half h = __float2half_rn(res);
        s_hi[t * LDC + c] = h;
        s_lo[t * LDC + c] = __float2half_rn(res - __half2float(h));
    }
    __syncthreads();

    for (int idx = t; idx < 256 * 16; idx += 256) {
        const int pp = idx >> 4, j = idx & 15;
        const uint2 vh = *reinterpret_cast<const uint2*>(s_hi + pp * LDC + j * 4);
        const uint2 vl = *reinterpret_cast<const uint2*>(s_lo + pp * LDC + j * 4);
        const size_t o = ((size_t)b * HWd + p0 + pp) * CIN + j * 4;
        *reinterpret_cast<uint2*>(xd_hi + o) = vh;
        *reinterpret_cast<uint2*>(xd_lo + o) = vl;
    }
}

// ---------------------------------------------------------------------------
extern "C" void kernel_launch(void* const* d_in, const int* in_sizes, int n_in,
                              void* d_out, int out_size)
{
    const float* x      = (const float*)d_in[0];
    const float* W_off  = (const float*)d_in[1];
    const float* W_conv = (const float*)d_in[2];
    const float* b_conv = (const float*)d_in[3];
    float* out = (float*)d_out;

    float  *off_p;
    __half *xt_hi, *xd_hi, *xd_lo, *wa_hi, *wb_hi;
    cudaGetSymbolAddress((void**)&off_p, g_off);
    cudaGetSymbolAddress((void**)&xt_hi, g_xt_hi);
    cudaGetSymbolAddress((void**)&xd_hi, g_xd_hi);
    cudaGetSymbolAddress((void**)&xd_lo, g_xd_lo);
    cudaGetSymbolAddress((void**)&wa_hi, g_wa_hi);
    cudaGetSymbolAddress((void**)&wb_hi, g_wb_hi);

    // smem: A bufs + 3 B shift slots (halves)
    const int SMEM_A = (2 * 130 * 72 + 3 * 128 * 72) * 2;   // 92736  (COMPS=1)
    const int SMEM_B = (4 * 130 * 72 + 3 *  64 * 72) * 2;   // 102528 (COMPS=2)
    const int SMEM_G = 2 * 256 * 68 * 2;                    // 69632
    cudaFuncSetAttribute((conv_mma_kernel<128, 2, 4, false>),
                         cudaFuncAttributeMaxDynamicSharedMemorySize, SMEM_A);
    cudaFuncSetAttribute((conv_mma_kernel<64, 4, 2, true>),
                         cudaFuncAttributeMaxDynamicSharedMemorySize, SMEM_B);
    cudaFuncSetAttribute(gather_kernel,
                         cudaFuncAttributeMaxDynamicSharedMemorySize, SMEM_G);

    // 0) layout transforms
    xpose_kernel<<<Bn * Hd, 256>>>(x, xt_hi);
    wsplit_kernel<<<(9 * 128 * CIN + 255) / 256, 256>>>(W_off,  wa_hi, 128);
    wsplit_kernel<<<(9 *  64 * CIN + 255) / 256, 256>>>(W_conv, wb_hi, 64);

    // 1) offset conv (64 -> 128), plain fp16 single product (precision slack)
    conv_mma_kernel<128, 2, 4, false><<<Bn * Hd, 256, SMEM_A>>>(
        xt_hi, nullptr, wa_hi, nullptr, off_p);

    // 2) plane-local deformable gather -> fp16 hi/lo pixel-major
    gather_kernel<<<dim3(HWd / 256, Bn), 256, SMEM_G>>>(x, off_p, xd_hi, xd_lo);

    // 3) main conv (64 -> 64) + bias, A hi/lo 2-product (22-bit A, fp16 W)
    conv_mma_kernel<64, 4, 2, true><<<Bn * Hd, 256, SMEM_B>>>(
        xd_hi, xd_lo, wb_hi, b_conv, out);
}

// round 12
// speedup vs baseline: 4.8792x; 1.4031x over previous
#include <cuda_runtime.h>
#include <cuda_fp16.h>
#include <cstdint>

#define Hd   128
#define Wd   128
#define CIN  64
#define HWd  (Hd * Wd)
#define Bn   8

// ---------------- scratch (device globals; allocation is forbidden) --------
__device__ __align__(16) float  g_off  [Bn * 2 * CIN * HWd];   // offsets (B,2C,H,W) fp32
__device__ __align__(16) __half g_xt_hi[Bn * HWd * CIN];       // x pixel-major fp16
__device__ __align__(16) __half g_xd_hi[Bn * HWd * CIN];       // xdef pixel-major fp16
__device__ __align__(16) __half g_wa_hi[9 * 128 * CIN];        // W_off  (s,O,I) fp16
__device__ __align__(16) __half g_wb_hi[9 *  64 * CIN];        // W_conv (s,O,I) fp16

// ---------------- helpers ---------------------------------------------------
__device__ __forceinline__ uint32_t smem_u32(const void* p) {
    uint32_t a;
    asm("{ .reg .u64 t; cvta.to.shared.u64 t, %1; cvt.u32.u64 %0, t; }"
        : "=r"(a) : "l"(p));
    return a;
}
__device__ __forceinline__ void ldx4(uint32_t& r0, uint32_t& r1, uint32_t& r2,
                                     uint32_t& r3, uint32_t addr) {
    asm volatile("ldmatrix.sync.aligned.m8n8.x4.shared.b16 {%0,%1,%2,%3}, [%4];"
                 : "=r"(r0), "=r"(r1), "=r"(r2), "=r"(r3) : "r"(addr));
}
__device__ __forceinline__ void mma16816(float* d, const uint32_t* a,
                                         uint32_t b0, uint32_t b1) {
    asm volatile("mma.sync.aligned.m16n8k16.row.col.f32.f16.f16.f32 "
                 "{%0,%1,%2,%3}, {%4,%5,%6,%7}, {%8,%9}, {%0,%1,%2,%3};"
                 : "+f"(d[0]), "+f"(d[1]), "+f"(d[2]), "+f"(d[3])
                 : "r"(a[0]), "r"(a[1]), "r"(a[2]), "r"(a[3]), "r"(b0), "r"(b1));
}
// cp.async 16B with zero-fill when pred==false (src still a valid address)
__device__ __forceinline__ void cpa16(uint32_t dst, const void* src, bool pred) {
    asm volatile("cp.async.cg.shared.global [%0], [%1], 16, %2;"
                 :: "r"(dst), "l"(src), "r"(pred ? 16u : 0u));
}
#define CP_COMMIT()  asm volatile("cp.async.commit_group;" ::: "memory")
#define CP_WAIT0()   asm volatile("cp.async.wait_group 0;" ::: "memory")

// ---------------------------------------------------------------------------
// Transpose to pixel-major fp16: x (B,C,H,W) f32 -> (B,H,W,C) half.
// ---------------------------------------------------------------------------
__global__ void __launch_bounds__(256)
xpose_kernel(const float* __restrict__ x, __half* __restrict__ hi)
{
    __shared__ float s[CIN][Wd + 1];
    const int tid = threadIdx.x;
    const int y = blockIdx.x & (Hd - 1);
    const int b = blockIdx.x >> 7;

    for (int idx = tid; idx < CIN * Wd; idx += 256) {
        const int c = idx >> 7, xx = idx & (Wd - 1);
        s[c][xx] = x[(((size_t)b * CIN + c) * Hd + y) * Wd + xx];
    }
    __syncthreads();
    for (int idx = tid; idx < Wd * (CIN / 2); idx += 256) {
        const int xx = idx >> 5, cp = idx & 31;
        const __half h0 = __float2half_rn(s[2 * cp][xx]);
        const __half h1 = __float2half_rn(s[2 * cp + 1][xx]);
        const size_t base = ((size_t)(b * Hd + y) * Wd + xx) * CIN + 2 * cp;
        *reinterpret_cast<__half2*>(hi + base) = __halves2half2(h0, h1);
    }
}

// ---------------------------------------------------------------------------
// Weight transform: W (O, CIN, 3, 3) f32 -> (s, O, CIN) fp16.
// ---------------------------------------------------------------------------
__global__ void __launch_bounds__(256)
wsplit_kernel(const float* __restrict__ w, __half* __restrict__ hi, int O)
{
    const int idx = blockIdx.x * 256 + threadIdx.x;
    if (idx >= 9 * O * CIN) return;
    const int i = idx & (CIN - 1);
    const int o = (idx >> 6) % O;
    const int s = idx / (CIN * O);
    hi[idx] = __float2half_rn(w[((size_t)o * CIN + i) * 9 + s]);
}

// ---------------------------------------------------------------------------
// Implicit-GEMM 3x3 conv via mma.sync (HMMA fp16, fp32 accum), dy-outer:
// A per-dy double-buffered (cp.async), B staged for all 3 dx of a dy.
// CTA = one (b, y) row: M=128 pixels, N=COUT.
// ---------------------------------------------------------------------------
template <int COUT, int WARPS_M, int WARPS_N>
__global__ void __launch_bounds__(256)
conv_mma_kernel(const __half* __restrict__ a_hi,
                const __half* __restrict__ w_hi,
                const float* __restrict__ bias, float* __restrict__ out)
{
    constexpr int WM = 128 / WARPS_M;
    constexpr int WN = COUT / WARPS_N;
    constexpr int MF = WM / 16;
    constexpr int NF = WN / 8;
    constexpr int LDA = 72;                  // 144B rows: ldmatrix conflict-free
    constexpr int LDB = 72;
    constexpr int ASEG = 130 * LDA;          // halves per A buffer
    constexpr int BSEG = COUT * LDB;         // halves per B shift slot
    constexpr int BOFF = 2 * ASEG;           // halves offset of B region (3 slots)

    extern __shared__ __align__(16) __half smem[];
    const uint32_t sb = smem_u32(smem);

    const int tid  = threadIdx.x;
    const int lane = tid & 31, wid = tid >> 5;
    const int wm = wid % WARPS_M, wn = wid / WARPS_M;
    const int m0 = wm * WM, n0 = wn * WN;
    const int y = blockIdx.x & (Hd - 1);
    const int b = blockIdx.x >> 7;

    auto stageA = [&](int buf, int dy) {
        const int yy = y + dy - 1;
        const bool rowok = (unsigned)yy < (unsigned)Hd;
        const uint32_t dh = sb + (uint32_t)(buf * ASEG) * 2;
        for (int idx = tid; idx < 130 * 8; idx += 256) {
            const int p = idx >> 3, j = idx & 7;
            const int xx = p - 1;
            const bool ok = rowok && (unsigned)xx < (unsigned)Wd;
            const size_t base = ok ? (((size_t)((b * Hd + yy) * Wd + xx)) * CIN + j * 8) : 0;
            const uint32_t doff = (uint32_t)(p * LDA + j * 8) * 2;
            cpa16(dh + doff, a_hi + base, ok);
        }
    };
    // stage B for all 3 dx shifts of row-group dy: [dx][COUT][LDB]
    auto stageB3 = [&](int dy) {
        const int s0 = dy * 3;
        const uint32_t dh = sb + (uint32_t)BOFF * 2;
        for (int idx = tid; idx < 3 * COUT * 8; idx += 256) {
            const int op = idx >> 3, j = idx & 7;      // op = dx*COUT + o
            const size_t base = ((size_t)(s0 * COUT) + op) * CIN + j * 8;
            const uint32_t doff = (uint32_t)(op * LDB + j * 8) * 2;
            cpa16(dh + doff, w_hi + base, true);
        }
    };

    float d[MF][NF][4];
#pragma unroll
    for (int i = 0; i < MF; i++)
#pragma unroll
        for (int j = 0; j < NF; j++)
#pragma unroll
            for (int k = 0; k < 4; k++) d[i][j][k] = 0.0f;

    const int a_row = lane & 15;
    const int a_k   = (lane >> 4) << 3;
    const int b_row = ((lane >> 4) << 3) + (lane & 7);
    const int b_k   = ((lane >> 3) & 1) << 3;

    // ---- prologue: A(dy0), A(dy1), B(dy0) in one group ----
    stageA(0, 0); stageA(1, 1); stageB3(0); CP_COMMIT();

#pragma unroll 1
    for (int dy = 0; dy < 3; dy++) {
        CP_WAIT0();
        __syncthreads();

        const uint32_t uAh = sb + (uint32_t)((dy & 1) * ASEG) * 2;

#pragma unroll 1
        for (int dx = 0; dx < 3; dx++) {
            const uint32_t uB = sb + (uint32_t)(BOFF + dx * BSEG) * 2;
#pragma unroll
            for (int kk = 0; kk < 4; kk++) {
                uint32_t ah[MF][4];
#pragma unroll
                for (int mf = 0; mf < MF; mf++) {
                    const uint32_t off =
                        (uint32_t)((m0 + mf * 16 + a_row + dx) * LDA + kk * 16 + a_k) * 2;
                    ldx4(ah[mf][0], ah[mf][1], ah[mf][2], ah[mf][3], uAh + off);
                }
#pragma unroll
                for (int nfp = 0; nfp < NF / 2; nfp++) {
                    const uint32_t boff =
                        (uint32_t)((n0 + nfp * 16 + b_row) * LDB + kk * 16 + b_k) * 2;
                    uint32_t h0, h1, h2, h3;
                    ldx4(h0, h1, h2, h3, uB + boff);
#pragma unroll
                    for (int mf = 0; mf < MF; mf++) {
                        mma16816(d[mf][2 * nfp],     ah[mf], h0, h1);
                        mma16816(d[mf][2 * nfp + 1], ah[mf], h2, h3);
                    }
                }
            }
        }
        __syncthreads();   // B slots + A buffer free to restage

        if (dy < 2) {
            if (dy == 0) stageA(0, 2);   // A(dy2) into buf 0
            stageB3(dy + 1);
        }
        CP_COMMIT();
    }

    // ---- single-pass epilogue through smem, coalesced STG ----
    float* sEp = reinterpret_cast<float*>(smem);   // COUT x 132
#pragma unroll
    for (int mf = 0; mf < MF; mf++) {
#pragma unroll
        for (int nf = 0; nf < NF; nf++) {
            const int xl = m0 + mf * 16 + (lane >> 2);
            const int c  = n0 + nf * 8 + (lane & 3) * 2;
            sEp[ c      * 132 + xl    ] = d[mf][nf][0];
            sEp[(c + 1) * 132 + xl    ] = d[mf][nf][1];
            sEp[ c      * 132 + xl + 8] = d[mf][nf][2];
            sEp[(c + 1) * 132 + xl + 8] = d[mf][nf][3];
        }
    }
    __syncthreads();
    for (int idx = tid; idx < COUT * 128; idx += 256) {
        const int c = idx >> 7, q = idx & 127;
        float v = sEp[c * 132 + q];
        if (bias) v += __ldg(bias + c);
        out[(((size_t)b * COUT + c) * Hd + y) * Wd + q] = v;
    }
}

// ---------------------------------------------------------------------------
// Plane-local deformable gather -> pixel-major fp16.
// Block = 256 consecutive pixels; loop over channels (sector locality).
// ---------------------------------------------------------------------------
__global__ void __launch_bounds__(256)
gather_kernel(const float* __restrict__ x,       // (B, C, H, W)
              const float* __restrict__ off,     // (B, 2C, H, W)
              __half* __restrict__ xd_hi)
{
    constexpr int LDC = 68;
    extern __shared__ __align__(16) __half gsm[]; // s_hi[256][68]
    __half* s_hi = gsm;

    const int t  = threadIdx.x;
    const int p0 = blockIdx.x * 256;
    const int b  = blockIdx.y;
    const int p  = p0 + t;

    const float gy = (float)(p >> 7);
    const float gx = (float)(p & 127);
    const int   t2 = 2 * p;
    const int   chb = t2 >> 14;
    const int   pos = t2 & (HWd - 1);
    const float* offb = off + (size_t)b * (2 * CIN) * HWd + pos;
    const float* xb   = x + (size_t)b * CIN * HWd;

#pragma unroll 1
    for (int c = 0; c < CIN; c++) {
        const float2 o2 = *reinterpret_cast<const float2*>(
            offb + (size_t)(2 * c + chb) * HWd);

        float cy = o2.x + gy;
        float cx = o2.y + gx;
        cy = fminf(fmaxf(cy, 0.0f), (float)(Hd - 1));
        cx = fminf(fmaxf(cx, 0.0f), (float)(Wd - 1));

        const float y0f = floorf(cy), y1f = ceilf(cy);
        const float x0f = floorf(cx), x1f = ceilf(cx);
        const int y0 = (int)y0f, y1 = (int)y1f;
        const int x0 = (int)x0f, x1 = (int)x1f;

        const float* xp = xb + (size_t)c * HWd;
        const float v_lt = xp[y0 * Wd + x0];
        const float v_rb = xp[y1 * Wd + x1];
        const float v_lb = xp[y0 * Wd + x1];
        const float v_rt = xp[y1 * Wd + x0];

        const float dyf = cy - y0f;
        const float dxf = cx - x0f;
        const float v_t = dyf * (v_rt - v_lt) + v_lt;
        const float v_b = dyf * (v_rb - v_lb) + v_lb;
        const float res = dxf * (v_b - v_t) + v_t;

        s_hi[t * LDC + c] = __float2half_rn(res);
    }
    __syncthreads();

    // coalesced pixel-major writes: per pixel 64 ch = 128B
    for (int idx = t; idx < 256 * 16; idx += 256) {
        const int pp = idx >> 4, j = idx & 15;
        const uint2 vh = *reinterpret_cast<const uint2*>(s_hi + pp * LDC + j * 4);
        const size_t o = ((size_t)b * HWd + p0 + pp) * CIN + j * 4;
        *reinterpret_cast<uint2*>(xd_hi + o) = vh;
    }
}

// ---------------------------------------------------------------------------
extern "C" void kernel_launch(void* const* d_in, const int* in_sizes, int n_in,
                              void* d_out, int out_size)
{
    const float* x      = (const float*)d_in[0];
    const float* W_off  = (const float*)d_in[1];
    const float* W_conv = (const float*)d_in[2];
    const float* b_conv = (const float*)d_in[3];
    float* out = (float*)d_out;

    float  *off_p;
    __half *xt_hi, *xd_hi, *wa_hi, *wb_hi;
    cudaGetSymbolAddress((void**)&off_p, g_off);
    cudaGetSymbolAddress((void**)&xt_hi, g_xt_hi);
    cudaGetSymbolAddress((void**)&xd_hi, g_xd_hi);
    cudaGetSymbolAddress((void**)&wa_hi, g_wa_hi);
    cudaGetSymbolAddress((void**)&wb_hi, g_wb_hi);

    // smem: 2 A bufs + 3 B shift slots (halves)
    const int SMEM_A = (2 * 130 * 72 + 3 * 128 * 72) * 2;   // 92736
    const int SMEM_B = (2 * 130 * 72 + 3 *  64 * 72) * 2;   // 65088
    const int SMEM_G = 256 * 68 * 2;                        // 34816
    cudaFuncSetAttribute((conv_mma_kernel<128, 2, 4>),
                         cudaFuncAttributeMaxDynamicSharedMemorySize, SMEM_A);
    cudaFuncSetAttribute((conv_mma_kernel<64, 4, 2>),
                         cudaFuncAttributeMaxDynamicSharedMemorySize, SMEM_B);
    cudaFuncSetAttribute(gather_kernel,
                         cudaFuncAttributeMaxDynamicSharedMemorySize, SMEM_G);

    // 0) layout transforms
    xpose_kernel<<<Bn * Hd, 256>>>(x, xt_hi);
    wsplit_kernel<<<(9 * 128 * CIN + 255) / 256, 256>>>(W_off,  wa_hi, 128);
    wsplit_kernel<<<(9 *  64 * CIN + 255) / 256, 256>>>(W_conv, wb_hi, 64);

    // 1) offset conv (64 -> 128), fp16 single product
    conv_mma_kernel<128, 2, 4><<<Bn * Hd, 256, SMEM_A>>>(
        xt_hi, wa_hi, nullptr, off_p);

    // 2) plane-local deformable gather -> fp16 pixel-major
    gather_kernel<<<dim3(HWd / 256, Bn), 256, SMEM_G>>>(x, off_p, xd_hi);

    // 3) main conv (64 -> 64) + bias, fp16 single product
    conv_mma_kernel<64, 4, 2><<<Bn * Hd, 256, SMEM_B>>>(
        xd_hi, wb_hi, b_conv, out);
}